// round 7
// baseline (speedup 1.0000x reference)
#include <cuda_runtime.h>
#include <cuda.h>
#include <cuda_bf16.h>
#include <math.h>
#include <stdint.h>

// Problem dims
#define T_STEPS 128
#define BB      256
#define DIN     1024
#define HH      1024
#define NQ      8
#define DD      2048
#define NC      4112          // useful columns: zf|zi|g|o|basef(8)|basei(8)
#define NPAD    4224          // 33 tiles of 128
#define K3      6144          // 3x-split K: [Xhi|Xlo|Xhi | HXhi|HXlo|HXhi]
#define SEGX    3072

// ---------------- persistent device scratch ----------------
__device__ float g_Wall[(size_t)NC * DD];
__device__ float g_ball[NPAD];
__device__ __align__(256) __nv_bfloat16 g_Bp[(size_t)NPAD * K3];   // [BXhi|BXhi|BXlo|BHhi|BHhi|BHlo]
__device__ __align__(256) __nv_bfloat16 g_Xp[(size_t)T_STEPS * BB * SEGX]; // per-t [Xhi|Xlo|Xhi]
__device__ __align__(256) __nv_bfloat16 g_Hp[(size_t)BB * SEGX];   // [HXhi|HXlo|HXhi]
__device__ float g_CT[(size_t)NPAD * BB];                          // C^T [n][b]
__device__ float g_CXT[HH * BB];                                   // cell state [h][b]

// ============================================================
// mma.sync GEMM: C^T[4224,256] = (A'[256,6144] @ B'^T)^T + bias
// Block 64(M)x128(N), 128 thr (4 warps, warp tile 32x64), BK=64, 4 stages.
// ============================================================
#define NT      96            // K3 / 64
#define APITCH  72            // bf16 elems per smem row (64 + 8 pad) = 144 B
#define ASTB    (64 * APITCH * 2)    // 9216
#define BSTB    (128 * APITCH * 2)   // 18432
#define STAGE_B (ASTB + BSTB)        // 27648
#define GSMEM   (4 * STAGE_B)        // 110592

__device__ __forceinline__ uint32_t smem_u32(const void* p) {
    uint32_t a;
    asm("{ .reg .u64 t; cvta.to.shared.u64 t, %1; cvt.u32.u64 %0, t; }" : "=r"(a) : "l"(p));
    return a;
}
__device__ __forceinline__ void cp_async16(uint32_t dst, const void* src) {
    asm volatile("cp.async.cg.shared.global [%0], [%1], 16;" :: "r"(dst), "l"(src));
}
__device__ __forceinline__ void ldmatrix_x4(uint32_t& r0, uint32_t& r1,
                                            uint32_t& r2, uint32_t& r3, uint32_t a) {
    asm volatile("ldmatrix.sync.aligned.m8n8.x4.shared.b16 {%0,%1,%2,%3}, [%4];"
                 : "=r"(r0), "=r"(r1), "=r"(r2), "=r"(r3) : "r"(a));
}
__device__ __forceinline__ void mma_bf16(float* c, const uint32_t* a,
                                         uint32_t b0, uint32_t b1) {
    asm volatile("mma.sync.aligned.m16n8k16.row.col.f32.bf16.bf16.f32 "
                 "{%0,%1,%2,%3}, {%4,%5,%6,%7}, {%8,%9}, {%0,%1,%2,%3};"
                 : "+f"(c[0]), "+f"(c[1]), "+f"(c[2]), "+f"(c[3])
                 : "r"(a[0]), "r"(a[1]), "r"(a[2]), "r"(a[3]), "r"(b0), "r"(b1));
}

__global__ __launch_bounds__(128, 1) void gemm_mma(const __nv_bfloat16* __restrict__ xp)
{
    extern __shared__ __align__(16) char smraw[];
    const uint32_t sb = smem_u32(smraw);
    const int tid = threadIdx.x, lane = tid & 31, wid = tid >> 5;
    const int wm = wid & 1, wn = wid >> 1;
    const int m0 = blockIdx.y * 64, n0 = blockIdx.x * 128;

    // load geometry
    const int arow = tid >> 1, acol = (tid & 1) * 32;   // A: 64B per thread
    const __nv_bfloat16* gB = g_Bp + (size_t)(n0 + tid) * K3;
    const uint32_t daBase = sb + (arow * APITCH + acol) * 2;
    const uint32_t dbBase = sb + ASTB + (tid * APITCH) * 2;

    auto issue = [&](int kt, int st) {
        const __nv_bfloat16* asrc;
        int kb;
        if (kt < 48) { asrc = xp;   kb = kt * 64; }
        else         { asrc = g_Hp; kb = (kt - 48) * 64; }
        const __nv_bfloat16* ga = asrc + (size_t)(m0 + arow) * SEGX + kb + acol;
        const uint32_t da = daBase + st * STAGE_B;
#pragma unroll
        for (int j = 0; j < 4; j++) cp_async16(da + j * 16, ga + j * 8);
        const __nv_bfloat16* gb = gB + kt * 64;
        const uint32_t db = dbBase + st * STAGE_B;
#pragma unroll
        for (int j = 0; j < 8; j++) cp_async16(db + j * 16, gb + j * 8);
    };

    float acc[2][8][4];
#pragma unroll
    for (int i = 0; i < 2; i++)
#pragma unroll
        for (int j = 0; j < 8; j++)
#pragma unroll
            for (int r = 0; r < 4; r++) acc[i][j][r] = 0.f;

    // ldmatrix addresses
    const uint32_t aA0 = sb + ((wm * 32 + (lane & 15)) * APITCH + (lane >> 4) * 8) * 2;
    const int brl = wn * 64 + (lane & 7) + ((lane >> 4) << 3);
    const uint32_t bA0 = sb + ASTB + (brl * APITCH + ((lane >> 3) & 1) * 8) * 2;

    // prologue: 3 stages
#pragma unroll
    for (int s = 0; s < 3; s++) {
        issue(s, s);
        asm volatile("cp.async.commit_group;");
    }

    for (int kt = 0; kt < NT; kt++) {
        asm volatile("cp.async.wait_group 2;");
        __syncthreads();
        if (kt + 3 < NT) issue(kt + 3, (kt + 3) & 3);
        asm volatile("cp.async.commit_group;");

        const int st = kt & 3;
        const uint32_t aB = aA0 + st * STAGE_B;
        const uint32_t bB = bA0 + st * STAGE_B;
#pragma unroll
        for (int kk = 0; kk < 4; kk++) {
            uint32_t a[2][4], b[4][4];
#pragma unroll
            for (int mf = 0; mf < 2; mf++)
                ldmatrix_x4(a[mf][0], a[mf][1], a[mf][2], a[mf][3],
                            aB + (mf * 16 * APITCH + kk * 16) * 2);
#pragma unroll
            for (int nf = 0; nf < 4; nf++)
                ldmatrix_x4(b[nf][0], b[nf][1], b[nf][2], b[nf][3],
                            bB + (nf * 16 * APITCH + kk * 16) * 2);
#pragma unroll
            for (int mf = 0; mf < 2; mf++)
#pragma unroll
                for (int nf = 0; nf < 4; nf++) {
                    mma_bf16(acc[mf][nf * 2 + 0], a[mf], b[nf][0], b[nf][1]);
                    mma_bf16(acc[mf][nf * 2 + 1], a[mf], b[nf][2], b[nf][3]);
                }
        }
    }

    // epilogue: g_CT[n][m] += bias
#pragma unroll
    for (int mf = 0; mf < 2; mf++) {
        const int mb = m0 + wm * 32 + mf * 16 + (lane >> 2);
#pragma unroll
        for (int q = 0; q < 8; q++) {
            const int nb = n0 + wn * 64 + q * 8 + 2 * (lane & 3);
            const float bl0 = __ldg(&g_ball[nb]), bl1 = __ldg(&g_ball[nb + 1]);
            g_CT[(size_t)nb * BB + mb]           = acc[mf][q][0] + bl0;
            g_CT[(size_t)(nb + 1) * BB + mb]     = acc[mf][q][1] + bl1;
            g_CT[(size_t)nb * BB + mb + 8]       = acc[mf][q][2] + bl0;
            g_CT[(size_t)(nb + 1) * BB + mb + 8] = acc[mf][q][3] + bl1;
        }
    }
}

// ============================================================
// prep kernels
// ============================================================
#define BM 64
#define BN 128
#define BK 16
__global__ __launch_bounds__(256) void gemm_generic(
    const float* __restrict__ A, int sA,
    const float* __restrict__ Bm, int sBn, int sBk,
    float* __restrict__ C, int ldc, int M, int N, int K)
{
    __shared__ float Ash[BK][BM + 1];
    __shared__ float Bsh[BK][BN + 1];
    int tid = threadIdx.x, tx = tid & 15, ty = tid >> 4;
    int m0 = blockIdx.y * BM, n0 = blockIdx.x * BN;
    float acc[4][8];
#pragma unroll
    for (int i = 0; i < 4; i++)
#pragma unroll
        for (int j = 0; j < 8; j++) acc[i][j] = 0.f;
    for (int k0 = 0; k0 < K; k0 += BK) {
#pragma unroll
        for (int r = 0; r < 4; r++) {
            int ml = ty + 16 * r, mm = m0 + ml;
            Ash[tx][ml] = (mm < M) ? A[(size_t)mm * sA + k0 + tx] : 0.f;
        }
#pragma unroll
        for (int r = 0; r < 8; r++) {
            int nl = ty + 16 * r, nn = n0 + nl;
            Bsh[tx][nl] = (nn < N) ? Bm[(size_t)nn * sBn + (size_t)(k0 + tx) * sBk] : 0.f;
        }
        __syncthreads();
#pragma unroll
        for (int kk = 0; kk < BK; kk++) {
            float a[4], b[8];
#pragma unroll
            for (int i = 0; i < 4; i++) a[i] = Ash[kk][ty + 16 * i];
#pragma unroll
            for (int j = 0; j < 8; j++) b[j] = Bsh[kk][tx + 16 * j];
#pragma unroll
            for (int i = 0; i < 4; i++)
#pragma unroll
                for (int j = 0; j < 8; j++) acc[i][j] += a[i] * b[j];
        }
        __syncthreads();
    }
#pragma unroll
    for (int i = 0; i < 4; i++) {
        int mm = m0 + ty + 16 * i;
        if (mm >= M) continue;
#pragma unroll
        for (int j = 0; j < 8; j++) {
            int nn = n0 + tx + 16 * j;
            if (nn < N) C[(size_t)mm * ldc + nn] = acc[i][j];
        }
    }
}

__global__ void zero_cx_kernel() {
    int idx = blockIdx.x * blockDim.x + threadIdx.x;
    if (idx < HH * BB) g_CXT[idx] = 0.f;
}
__global__ void zero_hp_kernel() {
    int idx = blockIdx.x * blockDim.x + threadIdx.x;
    if (idx < BB * SEGX) g_Hp[idx] = __float2bfloat16(0.f);
}
__global__ void copy_wuwo_kernel(const float* __restrict__ Wu, const float* __restrict__ Wo) {
    size_t idx = (size_t)blockIdx.x * blockDim.x + threadIdx.x;
    size_t total = (size_t)2 * 1024 * DD;
    if (idx < total) {
        float v = (idx < (size_t)1024 * DD) ? Wu[idx] : Wo[idx - (size_t)1024 * DD];
        g_Wall[(size_t)2048 * DD + idx] = v;
    }
}
// warp-per-row: ball[0..2047] = enc_{f,i} @ bq
__global__ void bias_enc_kernel(const float* __restrict__ encf, const float* __restrict__ enci,
                                const float* __restrict__ bq)
{
    int w = (blockIdx.x * blockDim.x + threadIdx.x) >> 5;
    int lane = threadIdx.x & 31;
    if (w >= 2048) return;
    const float* enc = (w < 1024) ? encf : enci;
    int row = w & 1023;
    float s = 0.f;
    for (int j = lane; j < 1024; j += 32) s += enc[row * 1024 + j] * bq[j];
#pragma unroll
    for (int o = 16; o > 0; o >>= 1) s += __shfl_xor_sync(0xFFFFFFFF, s, o);
    if (lane == 0) g_ball[w] = s;
}
__global__ void bias_copy_kernel(const float* __restrict__ bu, const float* __restrict__ bo) {
    int n = 2048 + blockIdx.x * blockDim.x + threadIdx.x;
    if (n < 3072) g_ball[n] = bu[n - 2048];
    else if (n < 4096) g_ball[n] = bo[n - 3072];
    else if (n >= 4112 && n < NPAD) g_ball[n] = 0.f;
}
// Wall rows 4096..4111 = w_{f,i} @ WqF/WqI  (coalesced along d)
__global__ void wb_rows_kernel(const float* __restrict__ wfw, const float* __restrict__ wiw) {
    int i16 = blockIdx.y;
    int d = blockIdx.x * 256 + threadIdx.x;
    int g = i16 >> 3, i = i16 & 7;
    const float* ww = g ? wiw : wfw;
    float s = 0.f;
    for (int j = 0; j < 1024; j++)
        s += __ldg(&ww[i * 1024 + j]) * g_Wall[(size_t)(g * 1024 + j) * DD + d];
    g_Wall[(size_t)(4096 + i16) * DD + d] = s;
}
// ball[4096..4111] = w_{f,i} @ (enc @ bq)   (warp per output)
__global__ void bias_wb_kernel(const float* __restrict__ wfw, const float* __restrict__ wiw) {
    int w = threadIdx.x >> 5, lane = threadIdx.x & 31;
    if (w >= 16) return;
    int g = w >> 3, i = w & 7;
    const float* ww = g ? wiw : wfw;
    const float* bb = g_ball + g * 1024;
    float s = 0.f;
    for (int j = lane; j < 1024; j += 32) s += ww[i * 1024 + j] * bb[j];
#pragma unroll
    for (int o = 16; o > 0; o >>= 1) s += __shfl_xor_sync(0xFFFFFFFF, s, o);
    if (lane == 0) g_ball[4096 + w] = s;
}
// B' segs: [BXhi|BXhi|BXlo|BHhi|BHhi|BHlo]
__global__ void bsplit_kernel() {
    size_t idx = (size_t)blockIdx.x * blockDim.x + threadIdx.x;
    if (idx >= (size_t)NPAD * K3) return;
    int n = (int)(idx / K3), c = (int)(idx % K3);
    int seg = c >> 10, j = c & 1023;
    int srccol = (seg < 3) ? j : 1024 + j;
    float v = (n < NC) ? g_Wall[(size_t)n * DD + srccol] : 0.f;
    __nv_bfloat16 hi = __float2bfloat16(v);
    bool lo = (seg == 2) || (seg == 5);
    g_Bp[idx] = lo ? __float2bfloat16(v - __bfloat162float(hi)) : hi;
}
// all X parts for all t: Xp[t][b] = [Xhi|Xlo|Xhi]
__global__ void xprep_kernel(const float* __restrict__ X) {
    size_t idx = (size_t)blockIdx.x * blockDim.x + threadIdx.x;
    if (idx >= (size_t)T_STEPS * BB * 1024) return;
    size_t tb = idx >> 10;
    int k = (int)(idx & 1023);
    float v = X[idx];
    __nv_bfloat16 hi = __float2bfloat16(v);
    __nv_bfloat16 lo = __float2bfloat16(v - __bfloat162float(hi));
    size_t base = tb * SEGX;
    g_Xp[base + k] = hi;
    g_Xp[base + 1024 + k] = lo;
    g_Xp[base + 2048 + k] = hi;
}

// ============================================================
// fused wire + LSTM update
// ============================================================
__device__ __forceinline__ float sigf(float x) { return 1.f / (1.f + expf(-x)); }

__global__ __launch_bounds__(256) void elem_kernel(
    float* __restrict__ out_t,
    const float* __restrict__ wfw, const float* __restrict__ wfb,
    const float* __restrict__ wiw, const float* __restrict__ wib)
{
    const int h = blockIdx.x;     // 0..1023
    const int b = threadIdx.x;    // 0..255
    float f_pre, i_pre;
    if (h < NQ) {
        // recompute wire chains in registers (only cols 0..7 depend on them)
        float df[NQ], di[NQ];
        f_pre = 0.f; i_pre = 0.f;
#pragma unroll
        for (int i = 0; i < NQ; i++) {
            float dot = g_CT[(size_t)(4096 + i) * BB + b] + __ldg(&wfb[i]);
#pragma unroll
            for (int k = 0; k < NQ; k++)
                if (k < i) dot += df[k] * __ldg(&wfw[i * 1024 + k]);
            float v = tanhf(dot);
            df[i] = v - g_CT[(size_t)i * BB + b];
            if (i == h) f_pre = v;
        }
#pragma unroll
        for (int i = 0; i < NQ; i++) {
            float dot = g_CT[(size_t)(4104 + i) * BB + b] + __ldg(&wib[i]);
#pragma unroll
            for (int k = 0; k < NQ; k++)
                if (k < i) dot += di[k] * __ldg(&wiw[i * 1024 + k]);
            float v = tanhf(dot);
            di[i] = v - g_CT[(size_t)(1024 + i) * BB + b];
            if (i == h) i_pre = v;
        }
    } else {
        f_pre = g_CT[(size_t)h * BB + b];
        i_pre = g_CT[(size_t)(1024 + h) * BB + b];
    }
    const float gg = tanhf(g_CT[(size_t)(2048 + h) * BB + b]);
    const float o  = sigf(g_CT[(size_t)(3072 + h) * BB + b]);
    const size_t p = (size_t)h * BB + b;
    const float c = sigf(f_pre) * g_CXT[p] + sigf(i_pre) * gg;
    g_CXT[p] = c;
    const float hv = o * tanhf(c);
    out_t[(size_t)b * HH + h] = hv;
    __nv_bfloat16 hi = __float2bfloat16(hv);
    __nv_bfloat16 lo = __float2bfloat16(hv - __bfloat162float(hi));
    const size_t base = (size_t)b * SEGX;
    g_Hp[base + h] = hi;
    g_Hp[base + 1024 + h] = lo;
    g_Hp[base + 2048 + h] = hi;
}

__global__ void tail_kernel(float* __restrict__ out) {
    int idx = blockIdx.x * blockDim.x + threadIdx.x;
    if (idx < BB * HH) {
        out[(size_t)T_STEPS * BB * HH + idx] = out[(size_t)(T_STEPS - 1) * BB * HH + idx];
        out[(size_t)T_STEPS * BB * HH + BB * HH + idx] =
            g_CXT[(size_t)(idx & 1023) * BB + (idx >> 10)];
    }
}

// ============================================================
// host
// ============================================================
extern "C" void kernel_launch(void* const* d_in, const int* in_sizes, int n_in,
                              void* d_out, int out_size)
{
    const float* X    = (const float*)d_in[0];
    const float* Wq   = (const float*)d_in[1];
    const float* bq   = (const float*)d_in[2];
    const float* encf = (const float*)d_in[3];
    const float* wfw  = (const float*)d_in[4];
    const float* wfb  = (const float*)d_in[5];
    const float* enci = (const float*)d_in[6];
    const float* wiw  = (const float*)d_in[7];
    const float* wib  = (const float*)d_in[8];
    const float* Wu   = (const float*)d_in[9];
    const float* bu   = (const float*)d_in[10];
    const float* Wo   = (const float*)d_in[11];
    const float* bo   = (const float*)d_in[12];
    float* out = (float*)d_out;

    float* Wall = nullptr; cudaGetSymbolAddress((void**)&Wall, g_Wall);
    __nv_bfloat16* Xp = nullptr; cudaGetSymbolAddress((void**)&Xp, g_Xp);

    static bool attr_done = false;
    if (!attr_done) {
        cudaFuncSetAttribute(gemm_mma, cudaFuncAttributeMaxDynamicSharedMemorySize, GSMEM);
        attr_done = true;
    }

    // ---- prep ----
    zero_cx_kernel<<<(HH * BB + 255) / 256, 256>>>();
    zero_hp_kernel<<<(BB * SEGX + 255) / 256, 256>>>();
    {
        size_t total = (size_t)2 * 1024 * DD;
        copy_wuwo_kernel<<<(unsigned)((total + 255) / 256), 256>>>(Wu, Wo);
    }
    bias_enc_kernel<<<256, 256>>>(encf, enci, bq);
    bias_copy_kernel<<<9, 256>>>(bu, bo);
    gemm_generic<<<dim3((DD + BN - 1) / BN, (1024 + BM - 1) / BM), 256>>>(
        encf, 1024, Wq, 1, DD, Wall, DD, 1024, DD, 1024);
    gemm_generic<<<dim3((DD + BN - 1) / BN, (1024 + BM - 1) / BM), 256>>>(
        enci, 1024, Wq, 1, DD, Wall + (size_t)1024 * DD, DD, 1024, DD, 1024);
    wb_rows_kernel<<<dim3(8, 16), 256>>>(wfw, wiw);
    bias_wb_kernel<<<1, 512>>>(wfw, wiw);
    {
        size_t total = (size_t)NPAD * K3;
        bsplit_kernel<<<(unsigned)((total + 255) / 256), 256>>>();
    }
    {
        size_t total = (size_t)T_STEPS * BB * 1024;
        xprep_kernel<<<(unsigned)((total + 255) / 256), 256>>>(X);
    }

    // ---- recurrence ----
    dim3 grid_mma(NPAD / 128, BB / 64);   // 33 x 4 = 132 CTAs
    for (int t = 0; t < T_STEPS; t++) {
        gemm_mma<<<grid_mma, 128, GSMEM>>>(Xp + (size_t)t * BB * SEGX);
        elem_kernel<<<1024, 256>>>(out + (size_t)t * BB * HH, wfw, wfb, wiw, wib);
    }
    tail_kernel<<<(BB * HH + 255) / 256, 256>>>(out);
}

// round 8
// speedup vs baseline: 1.4301x; 1.4301x over previous
#include <cuda_runtime.h>
#include <cuda.h>
#include <cuda_bf16.h>
#include <math.h>
#include <stdint.h>

// Problem dims
#define T_STEPS 128
#define BB      256
#define DIN     1024
#define HH      1024
#define NQ      8
#define DD      2048
#define NC      4112          // zf|zi|g|o|basef(8)|basei(8)
#define NPAD    4224          // 33 tiles of 128
#define K3      6144          // [Xhi|Xlo|Xhi | HXhi|HXlo|HXhi]
#define SEGX    3072
#define KZ      4             // split-K factor
#define NTL     48            // kt (BK=32) per CTA = (K3/32)/KZ

// ---------------- persistent device scratch ----------------
__device__ float g_Wall[(size_t)NC * DD];
__device__ float g_ball[NPAD];
__device__ __align__(256) __nv_bfloat16 g_Bp[(size_t)NPAD * K3];
__device__ __align__(256) __nv_bfloat16 g_Xp[(size_t)T_STEPS * BB * SEGX];
__device__ __align__(256) __nv_bfloat16 g_Hp[(size_t)BB * SEGX];
__device__ float g_CTp[(size_t)KZ * NPAD * BB];      // split-K partials, C^T [z][n][b]
__device__ float g_CXT[HH * BB];                     // cell state [h][b]

// ============================================================
// mma.sync GEMM, split-K: partial_z[n][b] += A'[b, kz] @ B'[n, kz]^T
// Block 256(M) x 128(N), 256 thr, 8 warps (4M x 2N), warp tile 64x64,
// BK=32, 4-stage cp.async.
// ============================================================
#define APITCH  40                       // 32 + 8 pad bf16
#define ASTB    (256 * APITCH * 2)       // 20480
#define BSTB    (128 * APITCH * 2)       // 10240
#define STAGE_B (ASTB + BSTB)            // 30720
#define GSMEM   (4 * STAGE_B)            // 122880

__device__ __forceinline__ uint32_t smem_u32(const void* p) {
    uint32_t a;
    asm("{ .reg .u64 t; cvta.to.shared.u64 t, %1; cvt.u32.u64 %0, t; }" : "=r"(a) : "l"(p));
    return a;
}
__device__ __forceinline__ void cp_async16(uint32_t dst, const void* src) {
    asm volatile("cp.async.cg.shared.global [%0], [%1], 16;" :: "r"(dst), "l"(src));
}
__device__ __forceinline__ void ldmatrix_x4(uint32_t& r0, uint32_t& r1,
                                            uint32_t& r2, uint32_t& r3, uint32_t a) {
    asm volatile("ldmatrix.sync.aligned.m8n8.x4.shared.b16 {%0,%1,%2,%3}, [%4];"
                 : "=r"(r0), "=r"(r1), "=r"(r2), "=r"(r3) : "r"(a));
}
__device__ __forceinline__ void mma_bf16(float* c, const uint32_t* a,
                                         uint32_t b0, uint32_t b1) {
    asm volatile("mma.sync.aligned.m16n8k16.row.col.f32.bf16.bf16.f32 "
                 "{%0,%1,%2,%3}, {%4,%5,%6,%7}, {%8,%9}, {%0,%1,%2,%3};"
                 : "+f"(c[0]), "+f"(c[1]), "+f"(c[2]), "+f"(c[3])
                 : "r"(a[0]), "r"(a[1]), "r"(a[2]), "r"(a[3]), "r"(b0), "r"(b1));
}

__global__ __launch_bounds__(256, 1) void gemm_mma(const __nv_bfloat16* __restrict__ xp)
{
    extern __shared__ __align__(16) char smraw[];
    const uint32_t sb = smem_u32(smraw);
    const int tid = threadIdx.x, lane = tid & 31, wid = tid >> 5;
    const int wm = wid >> 1, wn = wid & 1;         // warp tile (wm*64, wn*64)
    const int n0 = blockIdx.x * 128;
    const int z  = blockIdx.y;                     // 0..3

    const __nv_bfloat16* asrc = (z < 2) ? xp : g_Hp;
    const int kb0 = (z & 1) * (SEGX / 2);          // 0 or 1536 within segment triple
    const int ktg0 = z * NTL;                      // global kt offset into K3

    // A: thread t loads row t, 64B (4x16B)
    const __nv_bfloat16* gA = asrc + (size_t)tid * SEGX + kb0;
    const uint32_t daB = sb + (tid * APITCH) * 2;
    // B: thread t loads row t/2, 32B chunk t&1
    const int brow = tid >> 1, bch = tid & 1;
    const __nv_bfloat16* gB = g_Bp + (size_t)(n0 + brow) * K3 + (size_t)ktg0 * 32 + bch * 16;
    const uint32_t dbB = sb + ASTB + (brow * APITCH + bch * 16) * 2;

    auto issue = [&](int kt, int st) {
        const uint32_t da = daB + st * STAGE_B;
        const __nv_bfloat16* ga = gA + kt * 32;
#pragma unroll
        for (int j = 0; j < 4; j++) cp_async16(da + j * 16, ga + j * 8);
        const uint32_t db = dbB + st * STAGE_B;
        const __nv_bfloat16* gb = gB + kt * 32;
        cp_async16(db, gb);
        cp_async16(db + 16, gb + 8);
    };

    float acc[4][8][4];
#pragma unroll
    for (int i = 0; i < 4; i++)
#pragma unroll
        for (int j = 0; j < 8; j++)
#pragma unroll
            for (int r = 0; r < 4; r++) acc[i][j][r] = 0.f;

    // ldmatrix bases
    const uint32_t aA0 = sb + ((wm * 64 + (lane & 15)) * APITCH + (lane >> 4) * 8) * 2;
    const int brl = wn * 64 + (lane & 7) + ((lane >> 4) << 3);
    const uint32_t bA0 = sb + ASTB + (brl * APITCH + ((lane >> 3) & 1) * 8) * 2;

#pragma unroll
    for (int s = 0; s < 3; s++) {
        issue(s, s);
        asm volatile("cp.async.commit_group;");
    }

    for (int kt = 0; kt < NTL; kt++) {
        asm volatile("cp.async.wait_group 2;");
        __syncthreads();
        if (kt + 3 < NTL) issue(kt + 3, (kt + 3) & 3);
        asm volatile("cp.async.commit_group;");

        const int st = kt & 3;
        const uint32_t aB = aA0 + st * STAGE_B;
        const uint32_t bB = bA0 + st * STAGE_B;
#pragma unroll
        for (int kk = 0; kk < 2; kk++) {
            uint32_t a[4][4], b[4][4];
#pragma unroll
            for (int mf = 0; mf < 4; mf++)
                ldmatrix_x4(a[mf][0], a[mf][1], a[mf][2], a[mf][3],
                            aB + (mf * 16 * APITCH + kk * 16) * 2);
#pragma unroll
            for (int nf = 0; nf < 4; nf++)
                ldmatrix_x4(b[nf][0], b[nf][1], b[nf][2], b[nf][3],
                            bB + (nf * 16 * APITCH + kk * 16) * 2);
#pragma unroll
            for (int mf = 0; mf < 4; mf++)
#pragma unroll
                for (int nf = 0; nf < 4; nf++) {
                    mma_bf16(acc[mf][nf * 2 + 0], a[mf], b[nf][0], b[nf][1]);
                    mma_bf16(acc[mf][nf * 2 + 1], a[mf], b[nf][2], b[nf][3]);
                }
        }
    }

    // epilogue: raw partial -> g_CTp[z]
    float* ctp = g_CTp + (size_t)z * NPAD * BB;
#pragma unroll
    for (int mf = 0; mf < 4; mf++) {
        const int mb = wm * 64 + mf * 16 + (lane >> 2);
#pragma unroll
        for (int q = 0; q < 8; q++) {
            const int nb = n0 + wn * 64 + q * 8 + 2 * (lane & 3);
            ctp[(size_t)nb * BB + mb]           = acc[mf][q][0];
            ctp[(size_t)(nb + 1) * BB + mb]     = acc[mf][q][1];
            ctp[(size_t)nb * BB + mb + 8]       = acc[mf][q][2];
            ctp[(size_t)(nb + 1) * BB + mb + 8] = acc[mf][q][3];
        }
    }
}

// ============================================================
// prep kernels
// ============================================================
#define BM 64
#define BN 128
#define BK 16
__global__ __launch_bounds__(256) void gemm_generic(
    const float* __restrict__ A, int sA,
    const float* __restrict__ Bm, int sBn, int sBk,
    float* __restrict__ C, int ldc, int M, int N, int K)
{
    __shared__ float Ash[BK][BM + 1];
    __shared__ float Bsh[BK][BN + 1];
    int tid = threadIdx.x, tx = tid & 15, ty = tid >> 4;
    int m0 = blockIdx.y * BM, n0 = blockIdx.x * BN;
    float acc[4][8];
#pragma unroll
    for (int i = 0; i < 4; i++)
#pragma unroll
        for (int j = 0; j < 8; j++) acc[i][j] = 0.f;
    for (int k0 = 0; k0 < K; k0 += BK) {
#pragma unroll
        for (int r = 0; r < 4; r++) {
            int ml = ty + 16 * r, mm = m0 + ml;
            Ash[tx][ml] = (mm < M) ? A[(size_t)mm * sA + k0 + tx] : 0.f;
        }
#pragma unroll
        for (int r = 0; r < 8; r++) {
            int nl = ty + 16 * r, nn = n0 + nl;
            Bsh[tx][nl] = (nn < N) ? Bm[(size_t)nn * sBn + (size_t)(k0 + tx) * sBk] : 0.f;
        }
        __syncthreads();
#pragma unroll
        for (int kk = 0; kk < BK; kk++) {
            float a[4], b[8];
#pragma unroll
            for (int i = 0; i < 4; i++) a[i] = Ash[kk][ty + 16 * i];
#pragma unroll
            for (int j = 0; j < 8; j++) b[j] = Bsh[kk][tx + 16 * j];
#pragma unroll
            for (int i = 0; i < 4; i++)
#pragma unroll
                for (int j = 0; j < 8; j++) acc[i][j] += a[i] * b[j];
        }
        __syncthreads();
    }
#pragma unroll
    for (int i = 0; i < 4; i++) {
        int mm = m0 + ty + 16 * i;
        if (mm >= M) continue;
#pragma unroll
        for (int j = 0; j < 8; j++) {
            int nn = n0 + tx + 16 * j;
            if (nn < N) C[(size_t)mm * ldc + nn] = acc[i][j];
        }
    }
}

__global__ void zero_cx_kernel() {
    int idx = blockIdx.x * blockDim.x + threadIdx.x;
    if (idx < HH * BB) g_CXT[idx] = 0.f;
}
__global__ void zero_hp_kernel() {
    int idx = blockIdx.x * blockDim.x + threadIdx.x;
    if (idx < BB * SEGX) g_Hp[idx] = __float2bfloat16(0.f);
}
__global__ void copy_wuwo_kernel(const float* __restrict__ Wu, const float* __restrict__ Wo) {
    size_t idx = (size_t)blockIdx.x * blockDim.x + threadIdx.x;
    size_t total = (size_t)2 * 1024 * DD;
    if (idx < total) {
        float v = (idx < (size_t)1024 * DD) ? Wu[idx] : Wo[idx - (size_t)1024 * DD];
        g_Wall[(size_t)2048 * DD + idx] = v;
    }
}
__global__ void bias_enc_kernel(const float* __restrict__ encf, const float* __restrict__ enci,
                                const float* __restrict__ bq)
{
    int w = (blockIdx.x * blockDim.x + threadIdx.x) >> 5;
    int lane = threadIdx.x & 31;
    if (w >= 2048) return;
    const float* enc = (w < 1024) ? encf : enci;
    int row = w & 1023;
    float s = 0.f;
    for (int j = lane; j < 1024; j += 32) s += enc[row * 1024 + j] * bq[j];
#pragma unroll
    for (int o = 16; o > 0; o >>= 1) s += __shfl_xor_sync(0xFFFFFFFF, s, o);
    if (lane == 0) g_ball[w] = s;
}
__global__ void bias_copy_kernel(const float* __restrict__ bu, const float* __restrict__ bo) {
    int n = 2048 + blockIdx.x * blockDim.x + threadIdx.x;
    if (n < 3072) g_ball[n] = bu[n - 2048];
    else if (n < 4096) g_ball[n] = bo[n - 3072];
    else if (n >= 4112 && n < NPAD) g_ball[n] = 0.f;
}
__global__ void wb_rows_kernel(const float* __restrict__ wfw, const float* __restrict__ wiw) {
    int i16 = blockIdx.y;
    int d = blockIdx.x * 256 + threadIdx.x;
    int g = i16 >> 3, i = i16 & 7;
    const float* ww = g ? wiw : wfw;
    float s = 0.f;
    for (int j = 0; j < 1024; j++)
        s += __ldg(&ww[i * 1024 + j]) * g_Wall[(size_t)(g * 1024 + j) * DD + d];
    g_Wall[(size_t)(4096 + i16) * DD + d] = s;
}
__global__ void bias_wb_kernel(const float* __restrict__ wfw, const float* __restrict__ wiw) {
    int w = threadIdx.x >> 5, lane = threadIdx.x & 31;
    if (w >= 16) return;
    int g = w >> 3, i = w & 7;
    const float* ww = g ? wiw : wfw;
    const float* bb = g_ball + g * 1024;
    float s = 0.f;
    for (int j = lane; j < 1024; j += 32) s += ww[i * 1024 + j] * bb[j];
#pragma unroll
    for (int o = 16; o > 0; o >>= 1) s += __shfl_xor_sync(0xFFFFFFFF, s, o);
    if (lane == 0) g_ball[4096 + w] = s;
}
__global__ void bsplit_kernel() {
    size_t idx = (size_t)blockIdx.x * blockDim.x + threadIdx.x;
    if (idx >= (size_t)NPAD * K3) return;
    int n = (int)(idx / K3), c = (int)(idx % K3);
    int seg = c >> 10, j = c & 1023;
    int srccol = (seg < 3) ? j : 1024 + j;
    float v = (n < NC) ? g_Wall[(size_t)n * DD + srccol] : 0.f;
    __nv_bfloat16 hi = __float2bfloat16(v);
    bool lo = (seg == 2) || (seg == 5);
    g_Bp[idx] = lo ? __float2bfloat16(v - __bfloat162float(hi)) : hi;
}
__global__ void xprep_kernel(const float* __restrict__ X) {
    size_t idx = (size_t)blockIdx.x * blockDim.x + threadIdx.x;
    if (idx >= (size_t)T_STEPS * BB * 1024) return;
    size_t tb = idx >> 10;
    int k = (int)(idx & 1023);
    float v = X[idx];
    __nv_bfloat16 hi = __float2bfloat16(v);
    __nv_bfloat16 lo = __float2bfloat16(v - __bfloat162float(hi));
    size_t base = tb * SEGX;
    g_Xp[base + k] = hi;
    g_Xp[base + 1024 + k] = lo;
    g_Xp[base + 2048 + k] = hi;
}

// ============================================================
// fused wire + LSTM update (sums KZ partials + bias)
// ============================================================
__device__ __forceinline__ float sigf(float x) { return 1.f / (1.f + expf(-x)); }
__device__ __forceinline__ float rdct(int n, int b) {
    size_t p = (size_t)n * BB + b;
    const size_t S = (size_t)NPAD * BB;
    return g_CTp[p] + g_CTp[S + p] + g_CTp[2 * S + p] + g_CTp[3 * S + p] + __ldg(&g_ball[n]);
}

__global__ __launch_bounds__(256) void elem_kernel(
    float* __restrict__ out_t,
    const float* __restrict__ wfw, const float* __restrict__ wfb,
    const float* __restrict__ wiw, const float* __restrict__ wib)
{
    const int h = blockIdx.x;     // 0..1023
    const int b = threadIdx.x;    // 0..255
    float f_pre, i_pre;
    if (h < NQ) {
        float df[NQ], di[NQ];
        f_pre = 0.f; i_pre = 0.f;
#pragma unroll
        for (int i = 0; i < NQ; i++) {
            float dot = rdct(4096 + i, b) + __ldg(&wfb[i]);
#pragma unroll
            for (int k = 0; k < NQ; k++)
                if (k < i) dot += df[k] * __ldg(&wfw[i * 1024 + k]);
            float v = tanhf(dot);
            df[i] = v - rdct(i, b);
            if (i == h) f_pre = v;
        }
#pragma unroll
        for (int i = 0; i < NQ; i++) {
            float dot = rdct(4104 + i, b) + __ldg(&wib[i]);
#pragma unroll
            for (int k = 0; k < NQ; k++)
                if (k < i) dot += di[k] * __ldg(&wiw[i * 1024 + k]);
            float v = tanhf(dot);
            di[i] = v - rdct(1024 + i, b);
            if (i == h) i_pre = v;
        }
    } else {
        f_pre = rdct(h, b);
        i_pre = rdct(1024 + h, b);
    }
    const float gg = tanhf(rdct(2048 + h, b));
    const float o  = sigf(rdct(3072 + h, b));
    const size_t p = (size_t)h * BB + b;
    const float c = sigf(f_pre) * g_CXT[p] + sigf(i_pre) * gg;
    g_CXT[p] = c;
    const float hv = o * tanhf(c);
    out_t[(size_t)b * HH + h] = hv;
    __nv_bfloat16 hi = __float2bfloat16(hv);
    __nv_bfloat16 lo = __float2bfloat16(hv - __bfloat162float(hi));
    const size_t base = (size_t)b * SEGX;
    g_Hp[base + h] = hi;
    g_Hp[base + 1024 + h] = lo;
    g_Hp[base + 2048 + h] = hi;
}

__global__ void tail_kernel(float* __restrict__ out) {
    int idx = blockIdx.x * blockDim.x + threadIdx.x;
    if (idx < BB * HH) {
        out[(size_t)T_STEPS * BB * HH + idx] = out[(size_t)(T_STEPS - 1) * BB * HH + idx];
        out[(size_t)T_STEPS * BB * HH + BB * HH + idx] =
            g_CXT[(size_t)(idx & 1023) * BB + (idx >> 10)];
    }
}

// ============================================================
// host
// ============================================================
extern "C" void kernel_launch(void* const* d_in, const int* in_sizes, int n_in,
                              void* d_out, int out_size)
{
    const float* X    = (const float*)d_in[0];
    const float* Wq   = (const float*)d_in[1];
    const float* bq   = (const float*)d_in[2];
    const float* encf = (const float*)d_in[3];
    const float* wfw  = (const float*)d_in[4];
    const float* wfb  = (const float*)d_in[5];
    const float* enci = (const float*)d_in[6];
    const float* wiw  = (const float*)d_in[7];
    const float* wib  = (const float*)d_in[8];
    const float* Wu   = (const float*)d_in[9];
    const float* bu   = (const float*)d_in[10];
    const float* Wo   = (const float*)d_in[11];
    const float* bo   = (const float*)d_in[12];
    float* out = (float*)d_out;

    float* Wall = nullptr; cudaGetSymbolAddress((void**)&Wall, g_Wall);
    __nv_bfloat16* Xp = nullptr; cudaGetSymbolAddress((void**)&Xp, g_Xp);

    static bool attr_done = false;
    if (!attr_done) {
        cudaFuncSetAttribute(gemm_mma, cudaFuncAttributeMaxDynamicSharedMemorySize, GSMEM);
        attr_done = true;
    }

    // ---- prep ----
    zero_cx_kernel<<<(HH * BB + 255) / 256, 256>>>();
    zero_hp_kernel<<<(BB * SEGX + 255) / 256, 256>>>();
    {
        size_t total = (size_t)2 * 1024 * DD;
        copy_wuwo_kernel<<<(unsigned)((total + 255) / 256), 256>>>(Wu, Wo);
    }
    bias_enc_kernel<<<256, 256>>>(encf, enci, bq);
    bias_copy_kernel<<<9, 256>>>(bu, bo);
    gemm_generic<<<dim3((DD + BN - 1) / BN, (1024 + BM - 1) / BM), 256>>>(
        encf, 1024, Wq, 1, DD, Wall, DD, 1024, DD, 1024);
    gemm_generic<<<dim3((DD + BN - 1) / BN, (1024 + BM - 1) / BM), 256>>>(
        enci, 1024, Wq, 1, DD, Wall + (size_t)1024 * DD, DD, 1024, DD, 1024);
    wb_rows_kernel<<<dim3(8, 16), 256>>>(wfw, wiw);
    bias_wb_kernel<<<1, 512>>>(wfw, wiw);
    {
        size_t total = (size_t)NPAD * K3;
        bsplit_kernel<<<(unsigned)((total + 255) / 256), 256>>>();
    }
    {
        size_t total = (size_t)T_STEPS * BB * 1024;
        xprep_kernel<<<(unsigned)((total + 255) / 256), 256>>>(X);
    }

    // ---- recurrence ----
    dim3 grid_mma(NPAD / 128, KZ);   // 33 x 4 = 132 CTAs
    for (int t = 0; t < T_STEPS; t++) {
        gemm_mma<<<grid_mma, 256, GSMEM>>>(Xp + (size_t)t * BB * SEGX);
        elem_kernel<<<1024, 256>>>(out + (size_t)t * BB * HH, wfw, wfb, wiw, wib);
    }
    tail_kernel<<<(BB * HH + 255) / 256, 256>>>(out);
}

// round 9
// speedup vs baseline: 1.7701x; 1.2377x over previous
#include <cuda_runtime.h>
#include <cuda.h>
#include <cuda_fp16.h>
#include <math.h>
#include <stdint.h>

// Problem dims
#define T_STEPS 128
#define BB      256
#define DIN     1024
#define HH      1024
#define NQ      8
#define DD      2048
#define NC      4112          // zf|zi|g|o|basef(8)|basei(8)
#define NPAD    4224          // 33 tiles of 128
#define K2      4096          // fp16-2x folded K: [Xhi|Xlo|Hhi|Hlo]
#define SEG2    2048          // per-source segment pair width
#define KZ      4
#define NTL     32            // BK=32 iters per CTA (K2/32/KZ)
#define NCTA    132

// ---------------- persistent device scratch ----------------
__device__ float g_Wall[(size_t)NC * DD];
__device__ float g_ball[NPAD];
__device__ __align__(256) __half g_Bp[(size_t)NPAD * K2];            // [Wx|Wx|Wh|Wh] fp16
__device__ __align__(256) __half g_Xp[(size_t)T_STEPS * BB * SEG2];  // per-t [Xhi|Xlo]
__device__ __align__(256) __half g_Hp[(size_t)BB * SEG2];            // [Hhi|Hlo]
__device__ float g_CTp[(size_t)KZ * NPAD * BB];                      // split-K partials [z][n][b]
__device__ float g_CXT[HH * BB];                                     // cell state [h][b]
__device__ unsigned long long g_bar = 0;                             // monotonic ticket barrier

// ============================================================
// GEMM config: block 256(M) x 128(N), 8 warps (4Mx2N), warp 64x64,
// BK=32, 3-stage cp.async, fused elem phase after grid barrier.
// ============================================================
#define APITCH  40
#define ASTB    (256 * APITCH * 2)       // 20480
#define BSTB    (128 * APITCH * 2)       // 10240
#define STAGE_B (ASTB + BSTB)            // 30720
#define GSMEM   (3 * STAGE_B)            // 92160

__device__ __forceinline__ uint32_t smem_u32(const void* p) {
    uint32_t a;
    asm("{ .reg .u64 t; cvta.to.shared.u64 t, %1; cvt.u32.u64 %0, t; }" : "=r"(a) : "l"(p));
    return a;
}
__device__ __forceinline__ void cp_async16(uint32_t dst, const void* src) {
    asm volatile("cp.async.cg.shared.global [%0], [%1], 16;" :: "r"(dst), "l"(src));
}
__device__ __forceinline__ void ldmatrix_x4(uint32_t& r0, uint32_t& r1,
                                            uint32_t& r2, uint32_t& r3, uint32_t a) {
    asm volatile("ldmatrix.sync.aligned.m8n8.x4.shared.b16 {%0,%1,%2,%3}, [%4];"
                 : "=r"(r0), "=r"(r1), "=r"(r2), "=r"(r3) : "r"(a));
}
__device__ __forceinline__ void mma_f16(float* c, const uint32_t* a,
                                        uint32_t b0, uint32_t b1) {
    asm volatile("mma.sync.aligned.m16n8k16.row.col.f32.f16.f16.f32 "
                 "{%0,%1,%2,%3}, {%4,%5,%6,%7}, {%8,%9}, {%0,%1,%2,%3};"
                 : "+f"(c[0]), "+f"(c[1]), "+f"(c[2]), "+f"(c[3])
                 : "r"(a[0]), "r"(a[1]), "r"(a[2]), "r"(a[3]), "r"(b0), "r"(b1));
}
__device__ __forceinline__ float sigf(float x) { return 1.f / (1.f + expf(-x)); }
__device__ __forceinline__ float rdct(int n, int b) {
    size_t p = (size_t)n * BB + b;
    const size_t S = (size_t)NPAD * BB;
    return g_CTp[p] + g_CTp[S + p] + g_CTp[2 * S + p] + g_CTp[3 * S + p] + __ldg(&g_ball[n]);
}

__global__ __launch_bounds__(256, 1) void step_kernel(
    const __half* __restrict__ xp, float* __restrict__ out_t,
    const float* __restrict__ wfw, const float* __restrict__ wfb,
    const float* __restrict__ wiw, const float* __restrict__ wib)
{
    extern __shared__ __align__(16) char smraw[];
    const uint32_t sb = smem_u32(smraw);
    const int tid = threadIdx.x, lane = tid & 31, wid = tid >> 5;
    const int wm = wid >> 1, wn = wid & 1;
    const int n0 = blockIdx.x * 128;
    const int z  = blockIdx.y;                    // segment index 0..3

    const __half* asrc = (z < 2) ? xp : g_Hp;
    const int kb0 = (z & 1) << 10;                // hi or lo half of the pair

    // A: thread t loads row t, 64B
    const __half* gA = asrc + (size_t)tid * SEG2 + kb0;
    const uint32_t daB = sb + (tid * APITCH) * 2;
    // B: thread t loads row t/2, 32B chunk t&1
    const int brow = tid >> 1, bch = tid & 1;
    const __half* gB = g_Bp + (size_t)(n0 + brow) * K2 + (z << 10) + bch * 16;
    const uint32_t dbB = sb + ASTB + (brow * APITCH + bch * 16) * 2;

    auto issue = [&](int kt, int st) {
        const uint32_t da = daB + st * STAGE_B;
        const __half* ga = gA + kt * 32;
#pragma unroll
        for (int j = 0; j < 4; j++) cp_async16(da + j * 16, ga + j * 8);
        const uint32_t db = dbB + st * STAGE_B;
        const __half* gb = gB + kt * 32;
        cp_async16(db, gb);
        cp_async16(db + 16, gb + 8);
    };

    float acc[4][8][4];
#pragma unroll
    for (int i = 0; i < 4; i++)
#pragma unroll
        for (int j = 0; j < 8; j++)
#pragma unroll
            for (int r = 0; r < 4; r++) acc[i][j][r] = 0.f;

    const uint32_t aA0 = sb + ((wm * 64 + (lane & 15)) * APITCH + (lane >> 4) * 8) * 2;
    const int brl = wn * 64 + (lane & 7) + ((lane >> 4) << 3);
    const uint32_t bA0 = sb + ASTB + (brl * APITCH + ((lane >> 3) & 1) * 8) * 2;

#pragma unroll
    for (int s = 0; s < 2; s++) {
        issue(s, s);
        asm volatile("cp.async.commit_group;");
    }

    for (int kt = 0; kt < NTL; kt++) {
        asm volatile("cp.async.wait_group 1;");
        __syncthreads();
        if (kt + 2 < NTL) issue(kt + 2, (kt + 2) % 3);
        asm volatile("cp.async.commit_group;");

        const int st = kt % 3;
        const uint32_t aB = aA0 + st * STAGE_B;
        const uint32_t bB = bA0 + st * STAGE_B;
#pragma unroll
        for (int kk = 0; kk < 2; kk++) {
            uint32_t a[4][4], b[4][4];
#pragma unroll
            for (int mf = 0; mf < 4; mf++)
                ldmatrix_x4(a[mf][0], a[mf][1], a[mf][2], a[mf][3],
                            aB + (mf * 16 * APITCH + kk * 16) * 2);
#pragma unroll
            for (int nf = 0; nf < 4; nf++)
                ldmatrix_x4(b[nf][0], b[nf][1], b[nf][2], b[nf][3],
                            bB + (nf * 16 * APITCH + kk * 16) * 2);
#pragma unroll
            for (int mf = 0; mf < 4; mf++)
#pragma unroll
                for (int nf = 0; nf < 4; nf++) {
                    mma_f16(acc[mf][nf * 2 + 0], a[mf], b[nf][0], b[nf][1]);
                    mma_f16(acc[mf][nf * 2 + 1], a[mf], b[nf][2], b[nf][3]);
                }
        }
    }

    // store raw partial -> g_CTp[z]
    float* ctp = g_CTp + (size_t)z * NPAD * BB;
#pragma unroll
    for (int mf = 0; mf < 4; mf++) {
        const int mb = wm * 64 + mf * 16 + (lane >> 2);
#pragma unroll
        for (int q = 0; q < 8; q++) {
            const int nb = n0 + wn * 64 + q * 8 + 2 * (lane & 3);
            ctp[(size_t)nb * BB + mb]           = acc[mf][q][0];
            ctp[(size_t)(nb + 1) * BB + mb]     = acc[mf][q][1];
            ctp[(size_t)nb * BB + mb + 8]       = acc[mf][q][2];
            ctp[(size_t)(nb + 1) * BB + mb + 8] = acc[mf][q][3];
        }
    }

    // ---- grid barrier (monotonic tickets; replay-safe, no reset) ----
    if (tid == 0) {
        __threadfence();
        unsigned long long t0 = atomicAdd(&g_bar, 1ULL);
        unsigned long long tgt = (t0 / (unsigned long long)NCTA + 1ULL) * (unsigned long long)NCTA;
        while (*((volatile unsigned long long*)&g_bar) < tgt) { __nanosleep(32); }
        __threadfence();
    }
    __syncthreads();

    // ---- fused elem phase ----
    const int cta = blockIdx.y * 33 + blockIdx.x;
#pragma unroll 1
    for (int k = 0; k < 8; k++) {
        int id = cta * 256 + tid + k * (NCTA * 256);
        if (id >= BB * HH) break;
        int h = id >> 8, b = id & 255;
        float f_pre, i_pre;
        if (h < NQ) {
            float df[NQ], di[NQ];
            f_pre = 0.f; i_pre = 0.f;
#pragma unroll
            for (int i = 0; i < NQ; i++) {
                float dot = rdct(4096 + i, b) + __ldg(&wfb[i]);
#pragma unroll
                for (int kk = 0; kk < NQ; kk++)
                    if (kk < i) dot += df[kk] * __ldg(&wfw[i * 1024 + kk]);
                float v = tanhf(dot);
                df[i] = v - rdct(i, b);
                if (i == h) f_pre = v;
            }
#pragma unroll
            for (int i = 0; i < NQ; i++) {
                float dot = rdct(4104 + i, b) + __ldg(&wib[i]);
#pragma unroll
                for (int kk = 0; kk < NQ; kk++)
                    if (kk < i) dot += di[kk] * __ldg(&wiw[i * 1024 + kk]);
                float v = tanhf(dot);
                di[i] = v - rdct(1024 + i, b);
                if (i == h) i_pre = v;
            }
        } else {
            f_pre = rdct(h, b);
            i_pre = rdct(1024 + h, b);
        }
        const float gg = tanhf(rdct(2048 + h, b));
        const float o  = sigf(rdct(3072 + h, b));
        const size_t p = (size_t)h * BB + b;
        const float c = sigf(f_pre) * g_CXT[p] + sigf(i_pre) * gg;
        g_CXT[p] = c;
        const float hv = o * tanhf(c);
        out_t[(size_t)b * HH + h] = hv;
        __half hi = __float2half(hv);
        __half lo = __float2half(hv - __half2float(hi));
        g_Hp[(size_t)b * SEG2 + h] = hi;
        g_Hp[(size_t)b * SEG2 + 1024 + h] = lo;
    }
}

// ============================================================
// prep kernels
// ============================================================
#define BM 64
#define BN 128
#define BK 16
__global__ __launch_bounds__(256) void gemm_generic(
    const float* __restrict__ A, int sA,
    const float* __restrict__ Bm, int sBn, int sBk,
    float* __restrict__ C, int ldc, int M, int N, int K)
{
    __shared__ float Ash[BK][BM + 1];
    __shared__ float Bsh[BK][BN + 1];
    int tid = threadIdx.x, tx = tid & 15, ty = tid >> 4;
    int m0 = blockIdx.y * BM, n0 = blockIdx.x * BN;
    float acc[4][8];
#pragma unroll
    for (int i = 0; i < 4; i++)
#pragma unroll
        for (int j = 0; j < 8; j++) acc[i][j] = 0.f;
    for (int k0 = 0; k0 < K; k0 += BK) {
#pragma unroll
        for (int r = 0; r < 4; r++) {
            int ml = ty + 16 * r, mm = m0 + ml;
            Ash[tx][ml] = (mm < M) ? A[(size_t)mm * sA + k0 + tx] : 0.f;
        }
#pragma unroll
        for (int r = 0; r < 8; r++) {
            int nl = ty + 16 * r, nn = n0 + nl;
            Bsh[tx][nl] = (nn < N) ? Bm[(size_t)nn * sBn + (size_t)(k0 + tx) * sBk] : 0.f;
        }
        __syncthreads();
#pragma unroll
        for (int kk = 0; kk < BK; kk++) {
            float a[4], b[8];
#pragma unroll
            for (int i = 0; i < 4; i++) a[i] = Ash[kk][ty + 16 * i];
#pragma unroll
            for (int j = 0; j < 8; j++) b[j] = Bsh[kk][tx + 16 * j];
#pragma unroll
            for (int i = 0; i < 4; i++)
#pragma unroll
                for (int j = 0; j < 8; j++) acc[i][j] += a[i] * b[j];
        }
        __syncthreads();
    }
#pragma unroll
    for (int i = 0; i < 4; i++) {
        int mm = m0 + ty + 16 * i;
        if (mm >= M) continue;
#pragma unroll
        for (int j = 0; j < 8; j++) {
            int nn = n0 + tx + 16 * j;
            if (nn < N) C[(size_t)mm * ldc + nn] = acc[i][j];
        }
    }
}

__global__ void zero_cx_kernel() {
    int idx = blockIdx.x * blockDim.x + threadIdx.x;
    if (idx < HH * BB) g_CXT[idx] = 0.f;
}
__global__ void zero_hp_kernel() {
    int idx = blockIdx.x * blockDim.x + threadIdx.x;
    if (idx < BB * SEG2) g_Hp[idx] = __float2half(0.f);
}
__global__ void copy_wuwo_kernel(const float* __restrict__ Wu, const float* __restrict__ Wo) {
    size_t idx = (size_t)blockIdx.x * blockDim.x + threadIdx.x;
    size_t total = (size_t)2 * 1024 * DD;
    if (idx < total) {
        float v = (idx < (size_t)1024 * DD) ? Wu[idx] : Wo[idx - (size_t)1024 * DD];
        g_Wall[(size_t)2048 * DD + idx] = v;
    }
}
__global__ void bias_enc_kernel(const float* __restrict__ encf, const float* __restrict__ enci,
                                const float* __restrict__ bq)
{
    int w = (blockIdx.x * blockDim.x + threadIdx.x) >> 5;
    int lane = threadIdx.x & 31;
    if (w >= 2048) return;
    const float* enc = (w < 1024) ? encf : enci;
    int row = w & 1023;
    float s = 0.f;
    for (int j = lane; j < 1024; j += 32) s += enc[row * 1024 + j] * bq[j];
#pragma unroll
    for (int o = 16; o > 0; o >>= 1) s += __shfl_xor_sync(0xFFFFFFFF, s, o);
    if (lane == 0) g_ball[w] = s;
}
__global__ void bias_copy_kernel(const float* __restrict__ bu, const float* __restrict__ bo) {
    int n = 2048 + blockIdx.x * blockDim.x + threadIdx.x;
    if (n < 3072) g_ball[n] = bu[n - 2048];
    else if (n < 4096) g_ball[n] = bo[n - 3072];
    else if (n >= 4112 && n < NPAD) g_ball[n] = 0.f;
}
__global__ void wb_rows_kernel(const float* __restrict__ wfw, const float* __restrict__ wiw) {
    int i16 = blockIdx.y;
    int d = blockIdx.x * 256 + threadIdx.x;
    int g = i16 >> 3, i = i16 & 7;
    const float* ww = g ? wiw : wfw;
    float s = 0.f;
    for (int j = 0; j < 1024; j++)
        s += __ldg(&ww[i * 1024 + j]) * g_Wall[(size_t)(g * 1024 + j) * DD + d];
    g_Wall[(size_t)(4096 + i16) * DD + d] = s;
}
__global__ void bias_wb_kernel(const float* __restrict__ wfw, const float* __restrict__ wiw) {
    int w = threadIdx.x >> 5, lane = threadIdx.x & 31;
    if (w >= 16) return;
    int g = w >> 3, i = w & 7;
    const float* ww = g ? wiw : wfw;
    const float* bb = g_ball + g * 1024;
    float s = 0.f;
    for (int j = lane; j < 1024; j += 32) s += ww[i * 1024 + j] * bb[j];
#pragma unroll
    for (int o = 16; o > 0; o >>= 1) s += __shfl_xor_sync(0xFFFFFFFF, s, o);
    if (lane == 0) g_ball[4096 + w] = s;
}
// B' = [Wx | Wx | Wh | Wh] fp16 (hi precision only; A carries the split)
__global__ void bsplit_kernel() {
    size_t idx = (size_t)blockIdx.x * blockDim.x + threadIdx.x;
    if (idx >= (size_t)NPAD * K2) return;
    int n = (int)(idx / K2), c = (int)(idx % K2);
    int seg = c >> 10, j = c & 1023;
    int srccol = (seg < 2) ? j : 1024 + j;
    float v = (n < NC) ? g_Wall[(size_t)n * DD + srccol] : 0.f;
    g_Bp[idx] = __float2half(v);
}
// Xp[t][b] = [Xhi | Xlo] fp16
__global__ void xprep_kernel(const float* __restrict__ X) {
    size_t idx = (size_t)blockIdx.x * blockDim.x + threadIdx.x;
    if (idx >= (size_t)T_STEPS * BB * 1024) return;
    size_t tb = idx >> 10;
    int k = (int)(idx & 1023);
    float v = X[idx];
    __half hi = __float2half(v);
    __half lo = __float2half(v - __half2float(hi));
    size_t base = tb * SEG2;
    g_Xp[base + k] = hi;
    g_Xp[base + 1024 + k] = lo;
}

__global__ void tail_kernel(float* __restrict__ out) {
    int idx = blockIdx.x * blockDim.x + threadIdx.x;
    if (idx < BB * HH) {
        out[(size_t)T_STEPS * BB * HH + idx] = out[(size_t)(T_STEPS - 1) * BB * HH + idx];
        out[(size_t)T_STEPS * BB * HH + BB * HH + idx] =
            g_CXT[(size_t)(idx & 1023) * BB + (idx >> 10)];
    }
}

// ============================================================
// host
// ============================================================
extern "C" void kernel_launch(void* const* d_in, const int* in_sizes, int n_in,
                              void* d_out, int out_size)
{
    const float* X    = (const float*)d_in[0];
    const float* Wq   = (const float*)d_in[1];
    const float* bq   = (const float*)d_in[2];
    const float* encf = (const float*)d_in[3];
    const float* wfw  = (const float*)d_in[4];
    const float* wfb  = (const float*)d_in[5];
    const float* enci = (const float*)d_in[6];
    const float* wiw  = (const float*)d_in[7];
    const float* wib  = (const float*)d_in[8];
    const float* Wu   = (const float*)d_in[9];
    const float* bu   = (const float*)d_in[10];
    const float* Wo   = (const float*)d_in[11];
    const float* bo   = (const float*)d_in[12];
    float* out = (float*)d_out;

    float* Wall = nullptr; cudaGetSymbolAddress((void**)&Wall, g_Wall);
    __half* Xp = nullptr;  cudaGetSymbolAddress((void**)&Xp, g_Xp);

    static bool attr_done = false;
    if (!attr_done) {
        cudaFuncSetAttribute(step_kernel, cudaFuncAttributeMaxDynamicSharedMemorySize, GSMEM);
        attr_done = true;
    }

    // ---- prep ----
    zero_cx_kernel<<<(HH * BB + 255) / 256, 256>>>();
    zero_hp_kernel<<<(BB * SEG2 + 255) / 256, 256>>>();
    {
        size_t total = (size_t)2 * 1024 * DD;
        copy_wuwo_kernel<<<(unsigned)((total + 255) / 256), 256>>>(Wu, Wo);
    }
    bias_enc_kernel<<<256, 256>>>(encf, enci, bq);
    bias_copy_kernel<<<9, 256>>>(bu, bo);
    gemm_generic<<<dim3((DD + BN - 1) / BN, (1024 + BM - 1) / BM), 256>>>(
        encf, 1024, Wq, 1, DD, Wall, DD, 1024, DD, 1024);
    gemm_generic<<<dim3((DD + BN - 1) / BN, (1024 + BM - 1) / BM), 256>>>(
        enci, 1024, Wq, 1, DD, Wall + (size_t)1024 * DD, DD, 1024, DD, 1024);
    wb_rows_kernel<<<dim3(8, 16), 256>>>(wfw, wiw);
    bias_wb_kernel<<<1, 512>>>(wfw, wiw);
    {
        size_t total = (size_t)NPAD * K2;
        bsplit_kernel<<<(unsigned)((total + 255) / 256), 256>>>();
    }
    {
        size_t total = (size_t)T_STEPS * BB * 1024;
        xprep_kernel<<<(unsigned)((total + 255) / 256), 256>>>(X);
    }

    // ---- recurrence: one fused kernel per step ----
    dim3 grid_step(NPAD / 128, KZ);   // 33 x 4 = 132 CTAs (all resident: barrier-safe)
    for (int t = 0; t < T_STEPS; t++) {
        step_kernel<<<grid_step, 256, GSMEM>>>(
            Xp + (size_t)t * BB * SEG2, out + (size_t)t * BB * HH,
            wfw, wfb, wiw, wib);
    }
    tail_kernel<<<(BB * HH + 255) / 256, 256>>>(out);
}

// round 10
// speedup vs baseline: 2.6956x; 1.5228x over previous
#include <cuda_runtime.h>
#include <cuda.h>
#include <cuda_fp16.h>
#include <math.h>
#include <stdint.h>

// Problem dims
#define T_STEPS 128
#define BB      256
#define DIN     1024
#define HH      1024
#define NQ      8
#define DD      2048
#define NC      4112          // zf|zi|g|o|basef(8)|basei(8)
#define NPAD    4224          // 33 tiles of 128
#define K2      2048          // fp16-1x K: [X | H]
#define KZ      4             // split-K: 512 cols each
#define NTL     16            // BK=32 iters per CTA
#define NCTA    132

// ---------------- persistent device scratch ----------------
__device__ float g_Wall[(size_t)NC * DD];
__device__ float g_ball[NPAD];
__device__ __align__(256) __half g_Bp[(size_t)NPAD * K2];            // [Wx|Wh] fp16
__device__ __align__(256) __half g_Xp[(size_t)T_STEPS * BB * 1024];  // fp16(X)
__device__ __align__(256) __half g_Hp[(size_t)BB * 1024];            // fp16(hx)
__device__ float g_CTp[(size_t)KZ * NPAD * BB];                      // split-K partials [z][n][b]
__device__ float g_CXT[HH * BB];                                     // cell state [h][b]
__device__ unsigned long long g_bar = 0;                             // monotonic ticket barrier

// ============================================================
// GEMM config: block 256(M) x 128(N), 8 warps (4Mx2N), warp 64x64,
// BK=32, 3-stage cp.async; persistent over all timesteps.
// ============================================================
#define APITCH  40
#define ASTB    (256 * APITCH * 2)       // 20480
#define BSTB    (128 * APITCH * 2)       // 10240
#define STAGE_B (ASTB + BSTB)            // 30720
#define GSMEM   (3 * STAGE_B)            // 92160

__device__ __forceinline__ uint32_t smem_u32(const void* p) {
    uint32_t a;
    asm("{ .reg .u64 t; cvta.to.shared.u64 t, %1; cvt.u32.u64 %0, t; }" : "=r"(a) : "l"(p));
    return a;
}
__device__ __forceinline__ void cp_async16(uint32_t dst, const void* src) {
    asm volatile("cp.async.cg.shared.global [%0], [%1], 16;" :: "r"(dst), "l"(src));
}
__device__ __forceinline__ void ldmatrix_x4(uint32_t& r0, uint32_t& r1,
                                            uint32_t& r2, uint32_t& r3, uint32_t a) {
    asm volatile("ldmatrix.sync.aligned.m8n8.x4.shared.b16 {%0,%1,%2,%3}, [%4];"
                 : "=r"(r0), "=r"(r1), "=r"(r2), "=r"(r3) : "r"(a));
}
__device__ __forceinline__ void mma_f16(float* c, const uint32_t* a,
                                        uint32_t b0, uint32_t b1) {
    asm volatile("mma.sync.aligned.m16n8k16.row.col.f32.f16.f16.f32 "
                 "{%0,%1,%2,%3}, {%4,%5,%6,%7}, {%8,%9}, {%0,%1,%2,%3};"
                 : "+f"(c[0]), "+f"(c[1]), "+f"(c[2]), "+f"(c[3])
                 : "r"(a[0]), "r"(a[1]), "r"(a[2]), "r"(a[3]), "r"(b0), "r"(b1));
}
__device__ __forceinline__ float sigf(float x) { return 1.f / (1.f + expf(-x)); }
__device__ __forceinline__ float rdct(int n, int b) {
    size_t p = (size_t)n * BB + b;
    const size_t S = (size_t)NPAD * BB;
    return g_CTp[p] + g_CTp[S + p] + g_CTp[2 * S + p] + g_CTp[3 * S + p] + __ldg(&g_ball[n]);
}
__device__ __forceinline__ void grid_bar(int tid) {
    __syncthreads();
    if (tid == 0) {
        __threadfence();
        unsigned long long t0 = atomicAdd(&g_bar, 1ULL);
        unsigned long long tgt = (t0 / (unsigned long long)NCTA + 1ULL) * (unsigned long long)NCTA;
        while (*((volatile unsigned long long*)&g_bar) < tgt) { __nanosleep(64); }
        __threadfence();
    }
    __syncthreads();
}

__global__ __launch_bounds__(256, 1) void persist_kernel(
    const __half* __restrict__ xp0, float* __restrict__ out,
    const float* __restrict__ wfw, const float* __restrict__ wfb,
    const float* __restrict__ wiw, const float* __restrict__ wib)
{
    extern __shared__ __align__(16) char smraw[];
    const uint32_t sb = smem_u32(smraw);
    const int tid = threadIdx.x, lane = tid & 31, wid = tid >> 5;
    const int wm = wid >> 1, wn = wid & 1;
    const int n0 = blockIdx.x * 128;
    const int z  = blockIdx.y;                    // 0..3 -> K slice z*512
    const int koff = (z & 1) << 9;                // col offset within source (0/512)

    // B geometry (time-invariant)
    const int brow = tid >> 1, bch = tid & 1;
    const __half* gB = g_Bp + (size_t)(n0 + brow) * K2 + (z << 9) + bch * 16;
    const uint32_t dbB = sb + ASTB + (brow * APITCH + bch * 16) * 2;
    const uint32_t daB = sb + (tid * APITCH) * 2;

    const uint32_t aA0 = sb + ((wm * 64 + (lane & 15)) * APITCH + (lane >> 4) * 8) * 2;
    const int brl = wn * 64 + (lane & 7) + ((lane >> 4) << 3);
    const uint32_t bA0 = sb + ASTB + (brl * APITCH + ((lane >> 3) & 1) * 8) * 2;

    float* ctp = g_CTp + (size_t)z * NPAD * BB;
    const int cta = blockIdx.y * 33 + blockIdx.x;

    for (int t = 0; t < T_STEPS; t++) {
        const __half* asrc = (z < 2) ? (xp0 + (size_t)t * BB * 1024) : g_Hp;
        const __half* gA = asrc + (size_t)tid * 1024 + koff;

        auto issue = [&](int kt, int st) {
            const uint32_t da = daB + st * STAGE_B;
            const __half* ga = gA + kt * 32;
#pragma unroll
            for (int j = 0; j < 4; j++) cp_async16(da + j * 16, ga + j * 8);
            const uint32_t db = dbB + st * STAGE_B;
            const __half* gb = gB + kt * 32;
            cp_async16(db, gb);
            cp_async16(db + 16, gb + 8);
        };

        float acc[4][8][4];
#pragma unroll
        for (int i = 0; i < 4; i++)
#pragma unroll
            for (int j = 0; j < 8; j++)
#pragma unroll
                for (int r = 0; r < 4; r++) acc[i][j][r] = 0.f;

#pragma unroll
        for (int s = 0; s < 2; s++) {
            issue(s, s);
            asm volatile("cp.async.commit_group;");
        }

        for (int kt = 0; kt < NTL; kt++) {
            asm volatile("cp.async.wait_group 1;");
            __syncthreads();
            if (kt + 2 < NTL) issue(kt + 2, (kt + 2) % 3);
            asm volatile("cp.async.commit_group;");

            const int st = kt % 3;
            const uint32_t aB = aA0 + st * STAGE_B;
            const uint32_t bB = bA0 + st * STAGE_B;
#pragma unroll
            for (int kk = 0; kk < 2; kk++) {
                uint32_t a[4][4], b[4][4];
#pragma unroll
                for (int mf = 0; mf < 4; mf++)
                    ldmatrix_x4(a[mf][0], a[mf][1], a[mf][2], a[mf][3],
                                aB + (mf * 16 * APITCH + kk * 16) * 2);
#pragma unroll
                for (int nf = 0; nf < 4; nf++)
                    ldmatrix_x4(b[nf][0], b[nf][1], b[nf][2], b[nf][3],
                                bB + (nf * 16 * APITCH + kk * 16) * 2);
#pragma unroll
                for (int mf = 0; mf < 4; mf++)
#pragma unroll
                    for (int nf = 0; nf < 4; nf++) {
                        mma_f16(acc[mf][nf * 2 + 0], a[mf], b[nf][0], b[nf][1]);
                        mma_f16(acc[mf][nf * 2 + 1], a[mf], b[nf][2], b[nf][3]);
                    }
            }
            __syncthreads();
        }

        // store raw partial -> g_CTp[z]
#pragma unroll
        for (int mf = 0; mf < 4; mf++) {
            const int mb = wm * 64 + mf * 16 + (lane >> 2);
#pragma unroll
            for (int q = 0; q < 8; q++) {
                const int nb = n0 + wn * 64 + q * 8 + 2 * (lane & 3);
                ctp[(size_t)nb * BB + mb]           = acc[mf][q][0];
                ctp[(size_t)(nb + 1) * BB + mb]     = acc[mf][q][1];
                ctp[(size_t)nb * BB + mb + 8]       = acc[mf][q][2];
                ctp[(size_t)(nb + 1) * BB + mb + 8] = acc[mf][q][3];
            }
        }

        grid_bar(tid);   // all partials visible

        // ---- fused elem phase ----
        float* out_t = out + (size_t)t * BB * HH;
#pragma unroll 1
        for (int k = 0; k < 8; k++) {
            int id = cta * 256 + tid + k * (NCTA * 256);
            if (id >= BB * HH) break;
            int h = id >> 8, b = id & 255;
            float f_pre, i_pre;
            if (h < NQ) {
                float df[NQ], di[NQ];
                f_pre = 0.f; i_pre = 0.f;
#pragma unroll
                for (int i = 0; i < NQ; i++) {
                    float dot = rdct(4096 + i, b) + __ldg(&wfb[i]);
#pragma unroll
                    for (int kk = 0; kk < NQ; kk++)
                        if (kk < i) dot += df[kk] * __ldg(&wfw[i * 1024 + kk]);
                    float v = tanhf(dot);
                    df[i] = v - rdct(i, b);
                    if (i == h) f_pre = v;
                }
#pragma unroll
                for (int i = 0; i < NQ; i++) {
                    float dot = rdct(4104 + i, b) + __ldg(&wib[i]);
#pragma unroll
                    for (int kk = 0; kk < NQ; kk++)
                        if (kk < i) dot += di[kk] * __ldg(&wiw[i * 1024 + kk]);
                    float v = tanhf(dot);
                    di[i] = v - rdct(1024 + i, b);
                    if (i == h) i_pre = v;
                }
            } else {
                f_pre = rdct(h, b);
                i_pre = rdct(1024 + h, b);
            }
            const float gg = tanhf(rdct(2048 + h, b));
            const float o  = sigf(rdct(3072 + h, b));
            const size_t p = (size_t)h * BB + b;
            const float c = sigf(f_pre) * g_CXT[p] + sigf(i_pre) * gg;
            g_CXT[p] = c;
            const float hv = o * tanhf(c);
            out_t[(size_t)b * HH + h] = hv;
            g_Hp[(size_t)b * 1024 + h] = __float2half(hv);
        }

        grid_bar(tid);   // Hp complete; CTp reusable
    }
}

// ============================================================
// prep kernels
// ============================================================
#define BM 64
#define BN 128
#define BK 16
__global__ __launch_bounds__(256) void gemm_generic(
    const float* __restrict__ A, int sA,
    const float* __restrict__ Bm, int sBn, int sBk,
    float* __restrict__ C, int ldc, int M, int N, int K)
{
    __shared__ float Ash[BK][BM + 1];
    __shared__ float Bsh[BK][BN + 1];
    int tid = threadIdx.x, tx = tid & 15, ty = tid >> 4;
    int m0 = blockIdx.y * BM, n0 = blockIdx.x * BN;
    float acc[4][8];
#pragma unroll
    for (int i = 0; i < 4; i++)
#pragma unroll
        for (int j = 0; j < 8; j++) acc[i][j] = 0.f;
    for (int k0 = 0; k0 < K; k0 += BK) {
#pragma unroll
        for (int r = 0; r < 4; r++) {
            int ml = ty + 16 * r, mm = m0 + ml;
            Ash[tx][ml] = (mm < M) ? A[(size_t)mm * sA + k0 + tx] : 0.f;
        }
#pragma unroll
        for (int r = 0; r < 8; r++) {
            int nl = ty + 16 * r, nn = n0 + nl;
            Bsh[tx][nl] = (nn < N) ? Bm[(size_t)nn * sBn + (size_t)(k0 + tx) * sBk] : 0.f;
        }
        __syncthreads();
#pragma unroll
        for (int kk = 0; kk < BK; kk++) {
            float a[4], b[8];
#pragma unroll
            for (int i = 0; i < 4; i++) a[i] = Ash[kk][ty + 16 * i];
#pragma unroll
            for (int j = 0; j < 8; j++) b[j] = Bsh[kk][tx + 16 * j];
#pragma unroll
            for (int i = 0; i < 4; i++)
#pragma unroll
                for (int j = 0; j < 8; j++) acc[i][j] += a[i] * b[j];
        }
        __syncthreads();
    }
#pragma unroll
    for (int i = 0; i < 4; i++) {
        int mm = m0 + ty + 16 * i;
        if (mm >= M) continue;
#pragma unroll
        for (int j = 0; j < 8; j++) {
            int nn = n0 + tx + 16 * j;
            if (nn < N) C[(size_t)mm * ldc + nn] = acc[i][j];
        }
    }
}

__global__ void zero_cx_kernel() {
    int idx = blockIdx.x * blockDim.x + threadIdx.x;
    if (idx < HH * BB) g_CXT[idx] = 0.f;
}
__global__ void zero_hp_kernel() {
    int idx = blockIdx.x * blockDim.x + threadIdx.x;
    if (idx < BB * 1024) g_Hp[idx] = __float2half(0.f);
}
__global__ void copy_wuwo_kernel(const float* __restrict__ Wu, const float* __restrict__ Wo) {
    size_t idx = (size_t)blockIdx.x * blockDim.x + threadIdx.x;
    size_t total = (size_t)2 * 1024 * DD;
    if (idx < total) {
        float v = (idx < (size_t)1024 * DD) ? Wu[idx] : Wo[idx - (size_t)1024 * DD];
        g_Wall[(size_t)2048 * DD + idx] = v;
    }
}
__global__ void bias_enc_kernel(const float* __restrict__ encf, const float* __restrict__ enci,
                                const float* __restrict__ bq)
{
    int w = (blockIdx.x * blockDim.x + threadIdx.x) >> 5;
    int lane = threadIdx.x & 31;
    if (w >= 2048) return;
    const float* enc = (w < 1024) ? encf : enci;
    int row = w & 1023;
    float s = 0.f;
    for (int j = lane; j < 1024; j += 32) s += enc[row * 1024 + j] * bq[j];
#pragma unroll
    for (int o = 16; o > 0; o >>= 1) s += __shfl_xor_sync(0xFFFFFFFF, s, o);
    if (lane == 0) g_ball[w] = s;
}
__global__ void bias_copy_kernel(const float* __restrict__ bu, const float* __restrict__ bo) {
    int n = 2048 + blockIdx.x * blockDim.x + threadIdx.x;
    if (n < 3072) g_ball[n] = bu[n - 2048];
    else if (n < 4096) g_ball[n] = bo[n - 3072];
    else if (n >= 4112 && n < NPAD) g_ball[n] = 0.f;
}
__global__ void wb_rows_kernel(const float* __restrict__ wfw, const float* __restrict__ wiw) {
    int i16 = blockIdx.y;
    int d = blockIdx.x * 256 + threadIdx.x;
    int g = i16 >> 3, i = i16 & 7;
    const float* ww = g ? wiw : wfw;
    float s = 0.f;
    for (int j = 0; j < 1024; j++)
        s += __ldg(&ww[i * 1024 + j]) * g_Wall[(size_t)(g * 1024 + j) * DD + d];
    g_Wall[(size_t)(4096 + i16) * DD + d] = s;
}
__global__ void bias_wb_kernel(const float* __restrict__ wfw, const float* __restrict__ wiw) {
    int w = threadIdx.x >> 5, lane = threadIdx.x & 31;
    if (w >= 16) return;
    int g = w >> 3, i = w & 7;
    const float* ww = g ? wiw : wfw;
    const float* bb = g_ball + g * 1024;
    float s = 0.f;
    for (int j = lane; j < 1024; j += 32) s += ww[i * 1024 + j] * bb[j];
#pragma unroll
    for (int o = 16; o > 0; o >>= 1) s += __shfl_xor_sync(0xFFFFFFFF, s, o);
    if (lane == 0) g_ball[4096 + w] = s;
}
// B' = [Wx | Wh] fp16
__global__ void bsplit_kernel() {
    size_t idx = (size_t)blockIdx.x * blockDim.x + threadIdx.x;
    if (idx >= (size_t)NPAD * K2) return;
    int n = (int)(idx / K2), c = (int)(idx % K2);
    int seg = c >> 10, j = c & 1023;
    int srccol = seg ? (1024 + j) : j;
    float v = (n < NC) ? g_Wall[(size_t)n * DD + srccol] : 0.f;
    g_Bp[idx] = __float2half(v);
}
// Xp = fp16(X)
__global__ void xprep_kernel(const float* __restrict__ X) {
    size_t idx = (size_t)blockIdx.x * blockDim.x + threadIdx.x;
    if (idx < (size_t)T_STEPS * BB * 1024)
        g_Xp[idx] = __float2half(X[idx]);
}

__global__ void tail_kernel(float* __restrict__ out) {
    int idx = blockIdx.x * blockDim.x + threadIdx.x;
    if (idx < BB * HH) {
        out[(size_t)T_STEPS * BB * HH + idx] = out[(size_t)(T_STEPS - 1) * BB * HH + idx];
        out[(size_t)T_STEPS * BB * HH + BB * HH + idx] =
            g_CXT[(size_t)(idx & 1023) * BB + (idx >> 10)];
    }
}

// ============================================================
// host
// ============================================================
extern "C" void kernel_launch(void* const* d_in, const int* in_sizes, int n_in,
                              void* d_out, int out_size)
{
    const float* X    = (const float*)d_in[0];
    const float* Wq   = (const float*)d_in[1];
    const float* bq   = (const float*)d_in[2];
    const float* encf = (const float*)d_in[3];
    const float* wfw  = (const float*)d_in[4];
    const float* wfb  = (const float*)d_in[5];
    const float* enci = (const float*)d_in[6];
    const float* wiw  = (const float*)d_in[7];
    const float* wib  = (const float*)d_in[8];
    const float* Wu   = (const float*)d_in[9];
    const float* bu   = (const float*)d_in[10];
    const float* Wo   = (const float*)d_in[11];
    const float* bo   = (const float*)d_in[12];
    float* out = (float*)d_out;

    float* Wall = nullptr; cudaGetSymbolAddress((void**)&Wall, g_Wall);
    __half* Xp = nullptr;  cudaGetSymbolAddress((void**)&Xp, g_Xp);

    static bool attr_done = false;
    if (!attr_done) {
        cudaFuncSetAttribute(persist_kernel, cudaFuncAttributeMaxDynamicSharedMemorySize, GSMEM);
        attr_done = true;
    }

    // ---- prep ----
    zero_cx_kernel<<<(HH * BB + 255) / 256, 256>>>();
    zero_hp_kernel<<<(BB * 1024 + 255) / 256, 256>>>();
    {
        size_t total = (size_t)2 * 1024 * DD;
        copy_wuwo_kernel<<<(unsigned)((total + 255) / 256), 256>>>(Wu, Wo);
    }
    bias_enc_kernel<<<256, 256>>>(encf, enci, bq);
    bias_copy_kernel<<<9, 256>>>(bu, bo);
    gemm_generic<<<dim3((DD + BN - 1) / BN, (1024 + BM - 1) / BM), 256>>>(
        encf, 1024, Wq, 1, DD, Wall, DD, 1024, DD, 1024);
    gemm_generic<<<dim3((DD + BN - 1) / BN, (1024 + BM - 1) / BM), 256>>>(
        enci, 1024, Wq, 1, DD, Wall + (size_t)1024 * DD, DD, 1024, DD, 1024);
    wb_rows_kernel<<<dim3(8, 16), 256>>>(wfw, wiw);
    bias_wb_kernel<<<1, 512>>>(wfw, wiw);
    {
        size_t total = (size_t)NPAD * K2;
        bsplit_kernel<<<(unsigned)((total + 255) / 256), 256>>>();
    }
    {
        size_t total = (size_t)T_STEPS * BB * 1024;
        xprep_kernel<<<(unsigned)((total + 255) / 256), 256>>>(X);
    }

    // ---- recurrence: ONE persistent kernel for all 128 steps ----
    dim3 grid_step(NPAD / 128, KZ);   // 33 x 4 = 132 CTAs, all resident
    persist_kernel<<<grid_step, 256, GSMEM>>>(Xp, out, wfw, wfb, wiw, wib);

    tail_kernel<<<(BB * HH + 255) / 256, 256>>>(out);
}

// round 11
// speedup vs baseline: 3.0921x; 1.1471x over previous
#include <cuda_runtime.h>
#include <cuda.h>
#include <cuda_fp16.h>
#include <math.h>
#include <stdint.h>

// Problem dims
#define T_STEPS 128
#define BB      256
#define DIN     1024
#define HH      1024
#define NQ      8
#define DD      2048
#define NC      4112          // zf|zi|g|o|basef(8)|basei(8)
#define NPAD    4224          // 33 tiles of 128
#define NCTA    132

// ---------------- persistent device scratch ----------------
__device__ float g_Wall[(size_t)NC * DD];
__device__ float g_ball[NPAD];
__device__ __align__(256) __half g_Bpx[(size_t)NPAD * 1024];        // Wx fp16
__device__ __align__(256) __half g_Bph[(size_t)NPAD * 1024];        // Wh fp16
__device__ __align__(256) __half g_Xp[(size_t)T_STEPS * BB * 1024]; // fp16(X)
__device__ __align__(256) __half g_Hp[(size_t)BB * 1024];           // fp16(hx)
__device__ float g_CTh[(size_t)NPAD * BB];                          // H-part C^T
__device__ float g_CTx[2][(size_t)NPAD * BB];                       // X-part C^T (+bias), parity
__device__ float g_CXT[HH * BB];                                    // cell state [h][b]
__device__ unsigned long long g_bar = 0;

// ============================================================
// GEMM config: block 64(M) x 128(N), 8 gemm warps (2Mx4N), warp 32x32,
// BK=32, 3-stage cp.async. K=1024 always.
// ============================================================
#define APITCH  40
#define A_ST    (64 * APITCH * 2)        // 5120
#define B_ST    (128 * APITCH * 2)       // 10240
#define STG_B   (A_ST + B_ST)            // 15360
#define GSMEM   (3 * STG_B)              // 46080
#define NTL     32                        // 1024/32

__device__ __forceinline__ uint32_t smem_u32(const void* p) {
    uint32_t a;
    asm("{ .reg .u64 t; cvta.to.shared.u64 t, %1; cvt.u32.u64 %0, t; }" : "=r"(a) : "l"(p));
    return a;
}
__device__ __forceinline__ void cp_async16(uint32_t dst, const void* src) {
    asm volatile("cp.async.cg.shared.global [%0], [%1], 16;" :: "r"(dst), "l"(src));
}
__device__ __forceinline__ void ldmatrix_x4(uint32_t& r0, uint32_t& r1,
                                            uint32_t& r2, uint32_t& r3, uint32_t a) {
    asm volatile("ldmatrix.sync.aligned.m8n8.x4.shared.b16 {%0,%1,%2,%3}, [%4];"
                 : "=r"(r0), "=r"(r1), "=r"(r2), "=r"(r3) : "r"(a));
}
__device__ __forceinline__ void mma_f16(float* c, const uint32_t* a,
                                        uint32_t b0, uint32_t b1) {
    asm volatile("mma.sync.aligned.m16n8k16.row.col.f32.f16.f16.f32 "
                 "{%0,%1,%2,%3}, {%4,%5,%6,%7}, {%8,%9}, {%0,%1,%2,%3};"
                 : "+f"(c[0]), "+f"(c[1]), "+f"(c[2]), "+f"(c[3])
                 : "r"(a[0]), "r"(a[1]), "r"(a[2]), "r"(a[3]), "r"(b0), "r"(b1));
}
#define GBAR_WARPS() asm volatile("bar.sync 1, 256;" ::: "memory")

__device__ __forceinline__ float sigf(float x) {
    float e = __expf(-x);
    return __fdividef(1.f, 1.f + e);
}

// K=1024 GEMM tile: C[n0:n0+128][m0:m0+64] (+bias) — gemm warps only (tid<256)
__device__ __forceinline__ void gemm64(const __half* __restrict__ Asrc,
                                       const __half* __restrict__ Bsrc,
                                       float* __restrict__ Cdst,
                                       const float* __restrict__ bias,
                                       int m0, int n0, uint32_t sb, int tid)
{
    const int lane = tid & 31, wid = tid >> 5;
    const int wm = wid & 1, wn = wid >> 1;

    const int arow = tid >> 2, ach = tid & 3;
    const __half* gA = Asrc + (size_t)(m0 + arow) * 1024 + ach * 8;
    const uint32_t daB = sb + (arow * APITCH + ach * 8) * 2;
    const int brow = tid >> 1, bch = tid & 1;
    const __half* gB = Bsrc + (size_t)(n0 + brow) * 1024 + bch * 16;
    const uint32_t dbB = sb + A_ST + (brow * APITCH + bch * 16) * 2;

    float acc[2][4][4];
#pragma unroll
    for (int i = 0; i < 2; i++)
#pragma unroll
        for (int j = 0; j < 4; j++)
#pragma unroll
            for (int r = 0; r < 4; r++) acc[i][j][r] = 0.f;

    const uint32_t aA0 = sb + ((wm * 32 + (lane & 15)) * APITCH + (lane >> 4) * 8) * 2;
    const int brl = wn * 32 + (lane & 7) + ((lane >> 4) << 3);
    const uint32_t bA0 = sb + A_ST + (brl * APITCH + ((lane >> 3) & 1) * 8) * 2;

    auto issue = [&](int kt, int st) {
        cp_async16(daB + st * STG_B, gA + kt * 32);
        const uint32_t db = dbB + st * STG_B;
        const __half* gb = gB + kt * 32;
        cp_async16(db, gb);
        cp_async16(db + 16, gb + 8);
    };

#pragma unroll
    for (int s = 0; s < 2; s++) {
        issue(s, s);
        asm volatile("cp.async.commit_group;");
    }

    for (int kt = 0; kt < NTL; kt++) {
        asm volatile("cp.async.wait_group 1;");
        GBAR_WARPS();
        if (kt + 2 < NTL) issue(kt + 2, (kt + 2) % 3);
        asm volatile("cp.async.commit_group;");

        const int st = kt % 3;
        const uint32_t aB = aA0 + st * STG_B;
        const uint32_t bB = bA0 + st * STG_B;
#pragma unroll
        for (int kk = 0; kk < 2; kk++) {
            uint32_t a[2][4], b[2][4];
#pragma unroll
            for (int mf = 0; mf < 2; mf++)
                ldmatrix_x4(a[mf][0], a[mf][1], a[mf][2], a[mf][3],
                            aB + (mf * 16 * APITCH + kk * 16) * 2);
#pragma unroll
            for (int nf = 0; nf < 2; nf++)
                ldmatrix_x4(b[nf][0], b[nf][1], b[nf][2], b[nf][3],
                            bB + (nf * 16 * APITCH + kk * 16) * 2);
#pragma unroll
            for (int mf = 0; mf < 2; mf++)
#pragma unroll
                for (int nf = 0; nf < 2; nf++) {
                    mma_f16(acc[mf][nf * 2 + 0], a[mf], b[nf][0], b[nf][1]);
                    mma_f16(acc[mf][nf * 2 + 1], a[mf], b[nf][2], b[nf][3]);
                }
        }
    }

#pragma unroll
    for (int mf = 0; mf < 2; mf++) {
        const int mb = m0 + wm * 32 + mf * 16 + (lane >> 2);
#pragma unroll
        for (int j = 0; j < 4; j++) {
            const int nb = n0 + wn * 32 + j * 8 + 2 * (lane & 3);
            float b0 = 0.f, b1 = 0.f;
            if (bias) { b0 = __ldg(bias + nb); b1 = __ldg(bias + nb + 1); }
            Cdst[(size_t)nb * BB + mb]           = acc[mf][j][0] + b0;
            Cdst[(size_t)(nb + 1) * BB + mb]     = acc[mf][j][1] + b1;
            Cdst[(size_t)nb * BB + mb + 8]       = acc[mf][j][2] + b0;
            Cdst[(size_t)(nb + 1) * BB + mb + 8] = acc[mf][j][3] + b1;
        }
    }
}

__device__ __forceinline__ void grid_bar(int tid) {
    __syncthreads();
    if (tid == 0) {
        __threadfence();
        unsigned long long t0 = atomicAdd(&g_bar, 1ULL);
        unsigned long long tgt = (t0 / (unsigned long long)NCTA + 1ULL) * (unsigned long long)NCTA;
        while (*((volatile unsigned long long*)&g_bar) < tgt) { __nanosleep(64); }
        __threadfence();
    }
    __syncthreads();
}

// ============================================================
// Persistent kernel: 384 threads = 8 gemm warps + 4 elem warps (1/SMSP)
// ============================================================
__global__ __launch_bounds__(384, 1) void persist_kernel(
    float* __restrict__ out,
    const float* __restrict__ wfw, const float* __restrict__ wfb,
    const float* __restrict__ wiw, const float* __restrict__ wib)
{
    extern __shared__ __align__(16) char smraw[];
    const uint32_t sb = smem_u32(smraw);
    const int tid = threadIdx.x;
    const int n0 = blockIdx.x * 128, m0 = blockIdx.y * 64;
    const bool isg = tid < 256;
    const int cta = blockIdx.y * 33 + blockIdx.x;

    // prologue: X-GEMM for t=0 into parity 0
    if (isg) gemm64(g_Xp, g_Bpx, g_CTx[0], g_ball, m0, n0, sb, tid);
    grid_bar(tid);

    for (int t = 0; t < T_STEPS; t++) {
        // Phase A: H-GEMM(t)
        if (isg) gemm64(g_Hp, g_Bph, g_CTh, nullptr, m0, n0, sb, tid);
        grid_bar(tid);

        // Phase B: gemm warps -> X-GEMM(t+1); elem warps -> gates/state
        if (isg) {
            if (t + 1 < T_STEPS)
                gemm64(g_Xp + (size_t)(t + 1) * BB * 1024, g_Bpx,
                       g_CTx[(t + 1) & 1], g_ball, m0, n0, sb, tid);
        } else {
            const int tid2 = tid - 256;                 // 0..127
            const float* cth = g_CTh;
            const float* ctx = g_CTx[t & 1];
            float* out_t = out + (size_t)t * BB * HH;
#pragma unroll 1
            for (int k = 0; k < 16; k++) {
                int id = cta * 128 + tid2 + k * (NCTA * 128);
                if (id >= BB * HH) break;
                int h = id >> 8, b = id & 255;
                auto rd = [&](int n) {
                    size_t p = (size_t)n * BB + b;
                    return cth[p] + ctx[p];
                };
                float f_pre, i_pre;
                if (h < NQ) {
                    float df[NQ], di[NQ];
                    f_pre = 0.f; i_pre = 0.f;
#pragma unroll
                    for (int i = 0; i < NQ; i++) {
                        float dot = rd(4096 + i) + __ldg(&wfb[i]);
#pragma unroll
                        for (int kk = 0; kk < NQ; kk++)
                            if (kk < i) dot += df[kk] * __ldg(&wfw[i * 1024 + kk]);
                        float v = tanhf(dot);
                        df[i] = v - rd(i);
                        if (i == h) f_pre = v;
                    }
#pragma unroll
                    for (int i = 0; i < NQ; i++) {
                        float dot = rd(4104 + i) + __ldg(&wib[i]);
#pragma unroll
                        for (int kk = 0; kk < NQ; kk++)
                            if (kk < i) dot += di[kk] * __ldg(&wiw[i * 1024 + kk]);
                        float v = tanhf(dot);
                        di[i] = v - rd(1024 + i);
                        if (i == h) i_pre = v;
                    }
                } else {
                    f_pre = rd(h);
                    i_pre = rd(1024 + h);
                }
                const float gg = tanhf(rd(2048 + h));
                const float o  = sigf(rd(3072 + h));
                const size_t p = (size_t)h * BB + b;
                const float c = sigf(f_pre) * g_CXT[p] + sigf(i_pre) * gg;
                g_CXT[p] = c;
                const float hv = o * tanhf(c);
                out_t[(size_t)b * HH + h] = hv;
                g_Hp[(size_t)b * 1024 + h] = __float2half(hv);
            }
        }
        grid_bar(tid);
    }
}

// ============================================================
// prep kernels
// ============================================================
#define BM 64
#define BN 128
#define BK 16
__global__ __launch_bounds__(256) void gemm_generic(
    const float* __restrict__ A, int sA,
    const float* __restrict__ Bm, int sBn, int sBk,
    float* __restrict__ C, int ldc, int M, int N, int K)
{
    __shared__ float Ash[BK][BM + 1];
    __shared__ float Bsh[BK][BN + 1];
    int tid = threadIdx.x, tx = tid & 15, ty = tid >> 4;
    int m0 = blockIdx.y * BM, n0 = blockIdx.x * BN;
    float acc[4][8];
#pragma unroll
    for (int i = 0; i < 4; i++)
#pragma unroll
        for (int j = 0; j < 8; j++) acc[i][j] = 0.f;
    for (int k0 = 0; k0 < K; k0 += BK) {
#pragma unroll
        for (int r = 0; r < 4; r++) {
            int ml = ty + 16 * r, mm = m0 + ml;
            Ash[tx][ml] = (mm < M) ? A[(size_t)mm * sA + k0 + tx] : 0.f;
        }
#pragma unroll
        for (int r = 0; r < 8; r++) {
            int nl = ty + 16 * r, nn = n0 + nl;
            Bsh[tx][nl] = (nn < N) ? Bm[(size_t)nn * sBn + (size_t)(k0 + tx) * sBk] : 0.f;
        }
        __syncthreads();
#pragma unroll
        for (int kk = 0; kk < BK; kk++) {
            float a[4], b[8];
#pragma unroll
            for (int i = 0; i < 4; i++) a[i] = Ash[kk][ty + 16 * i];
#pragma unroll
            for (int j = 0; j < 8; j++) b[j] = Bsh[kk][tx + 16 * j];
#pragma unroll
            for (int i = 0; i < 4; i++)
#pragma unroll
                for (int j = 0; j < 8; j++) acc[i][j] += a[i] * b[j];
        }
        __syncthreads();
    }
#pragma unroll
    for (int i = 0; i < 4; i++) {
        int mm = m0 + ty + 16 * i;
        if (mm >= M) continue;
#pragma unroll
        for (int j = 0; j < 8; j++) {
            int nn = n0 + tx + 16 * j;
            if (nn < N) C[(size_t)mm * ldc + nn] = acc[i][j];
        }
    }
}

__global__ void zero_cx_kernel() {
    int idx = blockIdx.x * blockDim.x + threadIdx.x;
    if (idx < HH * BB) g_CXT[idx] = 0.f;
}
__global__ void zero_hp_kernel() {
    int idx = blockIdx.x * blockDim.x + threadIdx.x;
    if (idx < BB * 1024) g_Hp[idx] = __float2half(0.f);
}
__global__ void copy_wuwo_kernel(const float* __restrict__ Wu, const float* __restrict__ Wo) {
    size_t idx = (size_t)blockIdx.x * blockDim.x + threadIdx.x;
    size_t total = (size_t)2 * 1024 * DD;
    if (idx < total) {
        float v = (idx < (size_t)1024 * DD) ? Wu[idx] : Wo[idx - (size_t)1024 * DD];
        g_Wall[(size_t)2048 * DD + idx] = v;
    }
}
__global__ void bias_enc_kernel(const float* __restrict__ encf, const float* __restrict__ enci,
                                const float* __restrict__ bq)
{
    int w = (blockIdx.x * blockDim.x + threadIdx.x) >> 5;
    int lane = threadIdx.x & 31;
    if (w >= 2048) return;
    const float* enc = (w < 1024) ? encf : enci;
    int row = w & 1023;
    float s = 0.f;
    for (int j = lane; j < 1024; j += 32) s += enc[row * 1024 + j] * bq[j];
#pragma unroll
    for (int o = 16; o > 0; o >>= 1) s += __shfl_xor_sync(0xFFFFFFFF, s, o);
    if (lane == 0) g_ball[w] = s;
}
__global__ void bias_copy_kernel(const float* __restrict__ bu, const float* __restrict__ bo) {
    int n = 2048 + blockIdx.x * blockDim.x + threadIdx.x;
    if (n < 3072) g_ball[n] = bu[n - 2048];
    else if (n < 4096) g_ball[n] = bo[n - 3072];
    else if (n >= 4112 && n < NPAD) g_ball[n] = 0.f;
}
__global__ void wb_rows_kernel(const float* __restrict__ wfw, const float* __restrict__ wiw) {
    int i16 = blockIdx.y;
    int d = blockIdx.x * 256 + threadIdx.x;
    int g = i16 >> 3, i = i16 & 7;
    const float* ww = g ? wiw : wfw;
    float s = 0.f;
    for (int j = 0; j < 1024; j++)
        s += __ldg(&ww[i * 1024 + j]) * g_Wall[(size_t)(g * 1024 + j) * DD + d];
    g_Wall[(size_t)(4096 + i16) * DD + d] = s;
}
__global__ void bias_wb_kernel(const float* __restrict__ wfw, const float* __restrict__ wiw) {
    int w = threadIdx.x >> 5, lane = threadIdx.x & 31;
    if (w >= 16) return;
    int g = w >> 3, i = w & 7;
    const float* ww = g ? wiw : wfw;
    const float* bb = g_ball + g * 1024;
    float s = 0.f;
    for (int j = lane; j < 1024; j += 32) s += ww[i * 1024 + j] * bb[j];
#pragma unroll
    for (int o = 16; o > 0; o >>= 1) s += __shfl_xor_sync(0xFFFFFFFF, s, o);
    if (lane == 0) g_ball[4096 + w] = s;
}
// Bpx[n][k] = Wall[n][k], Bph[n][k] = Wall[n][1024+k]
__global__ void bsplit_kernel() {
    size_t idx = (size_t)blockIdx.x * blockDim.x + threadIdx.x;
    if (idx >= (size_t)NPAD * 2048) return;
    int n = (int)(idx / 2048), c = (int)(idx % 2048);
    float v = (n < NC) ? g_Wall[(size_t)n * DD + c] : 0.f;
    if (c < 1024) g_Bpx[(size_t)n * 1024 + c] = __float2half(v);
    else          g_Bph[(size_t)n * 1024 + (c - 1024)] = __float2half(v);
}
__global__ void xprep_kernel(const float* __restrict__ X) {
    size_t idx = (size_t)blockIdx.x * blockDim.x + threadIdx.x;
    if (idx < (size_t)T_STEPS * BB * 1024)
        g_Xp[idx] = __float2half(X[idx]);
}

__global__ void tail_kernel(float* __restrict__ out) {
    int idx = blockIdx.x * blockDim.x + threadIdx.x;
    if (idx < BB * HH) {
        out[(size_t)T_STEPS * BB * HH + idx] = out[(size_t)(T_STEPS - 1) * BB * HH + idx];
        out[(size_t)T_STEPS * BB * HH + BB * HH + idx] =
            g_CXT[(size_t)(idx & 1023) * BB + (idx >> 10)];
    }
}

// ============================================================
// host
// ============================================================
extern "C" void kernel_launch(void* const* d_in, const int* in_sizes, int n_in,
                              void* d_out, int out_size)
{
    const float* X    = (const float*)d_in[0];
    const float* Wq   = (const float*)d_in[1];
    const float* bq   = (const float*)d_in[2];
    const float* encf = (const float*)d_in[3];
    const float* wfw  = (const float*)d_in[4];
    const float* wfb  = (const float*)d_in[5];
    const float* enci = (const float*)d_in[6];
    const float* wiw  = (const float*)d_in[7];
    const float* wib  = (const float*)d_in[8];
    const float* Wu   = (const float*)d_in[9];
    const float* bu   = (const float*)d_in[10];
    const float* Wo   = (const float*)d_in[11];
    const float* bo   = (const float*)d_in[12];
    float* out = (float*)d_out;

    float* Wall = nullptr; cudaGetSymbolAddress((void**)&Wall, g_Wall);

    static bool attr_done = false;
    if (!attr_done) {
        cudaFuncSetAttribute(persist_kernel, cudaFuncAttributeMaxDynamicSharedMemorySize, GSMEM);
        attr_done = true;
    }

    // ---- prep ----
    zero_cx_kernel<<<(HH * BB + 255) / 256, 256>>>();
    zero_hp_kernel<<<(BB * 1024 + 255) / 256, 256>>>();
    {
        size_t total = (size_t)2 * 1024 * DD;
        copy_wuwo_kernel<<<(unsigned)((total + 255) / 256), 256>>>(Wu, Wo);
    }
    bias_enc_kernel<<<256, 256>>>(encf, enci, bq);
    bias_copy_kernel<<<9, 256>>>(bu, bo);
    gemm_generic<<<dim3((DD + BN - 1) / BN, (1024 + BM - 1) / BM), 256>>>(
        encf, 1024, Wq, 1, DD, Wall, DD, 1024, DD, 1024);
    gemm_generic<<<dim3((DD + BN - 1) / BN, (1024 + BM - 1) / BM), 256>>>(
        enci, 1024, Wq, 1, DD, Wall + (size_t)1024 * DD, DD, 1024, DD, 1024);
    wb_rows_kernel<<<dim3(8, 16), 256>>>(wfw, wiw);
    bias_wb_kernel<<<1, 512>>>(wfw, wiw);
    {
        size_t total = (size_t)NPAD * 2048;
        bsplit_kernel<<<(unsigned)((total + 255) / 256), 256>>>();
    }
    {
        size_t total = (size_t)T_STEPS * BB * 1024;
        xprep_kernel<<<(unsigned)((total + 255) / 256), 256>>>(X);
    }

    // ---- recurrence: ONE persistent kernel, elem overlapped with X-GEMM ----
    dim3 grid_step(33, 4);   // 132 CTAs, all resident
    persist_kernel<<<grid_step, 384, GSMEM>>>(out, wfw, wfb, wiw, wib);

    tail_kernel<<<(BB * HH + 255) / 256, 256>>>(out);
}